// round 2
// baseline (speedup 1.0000x reference)
#include <cuda_runtime.h>

// Problem constants
#define B_    2
#define T_    2048
#define C_    1024
#define NH_   16
#define HD_   64
#define M_    (B_ * T_)     // 4096 rows
#define NQKV_ (3 * C_)      // 3072

// Scratch (device globals: allocation-free)
__device__ float g_qkv[(size_t)M_ * NQKV_];   // (B*T, 3C)
__device__ float g_att[(size_t)M_ * C_];      // (B*T, C) attention output

// ---------------------------------------------------------------------------
// SGEMM + bias: C[M,N] = A[M,K] @ B[K,N] + bias[N]
// 128x128x16 tiles, 256 threads, 8x8 microtile (1 B LDS per lane-FMA: balanced
// against the 128B/cyc smem crossbar vs 128 FMA/cyc/SM fp32 pipe).
// ---------------------------------------------------------------------------
__global__ __launch_bounds__(256, 2)
void sgemm_bias(const float* __restrict__ A, const float* __restrict__ Bm,
                const float* __restrict__ bias, float* __restrict__ Cm,
                int M, int N, int K) {
    __shared__ __align__(16) float As[16][132];   // A^T tile: [k][m], pad 4
    __shared__ __align__(16) float Bs[16][128];   // B tile:   [k][n]

    const int tid = threadIdx.x;
    const int tx  = tid & 15;    // 0..15 -> n microtile
    const int ty  = tid >> 4;    // 0..15 -> m microtile
    const int row0 = blockIdx.y * 128;
    const int col0 = blockIdx.x * 128;

    float acc[8][8];
#pragma unroll
    for (int i = 0; i < 8; i++)
#pragma unroll
        for (int j = 0; j < 8; j++) acc[i][j] = 0.f;

    for (int k0 = 0; k0 < K; k0 += 16) {
        // Load A tile (128 rows x 16 cols) as float4, store transposed.
#pragma unroll
        for (int t = tid; t < 512; t += 256) {
            int r  = t >> 2;           // 0..127
            int kc = (t & 3) << 2;     // 0,4,8,12
            float4 v = *reinterpret_cast<const float4*>(
                &A[(size_t)(row0 + r) * K + k0 + kc]);
            As[kc + 0][r] = v.x;
            As[kc + 1][r] = v.y;
            As[kc + 2][r] = v.z;
            As[kc + 3][r] = v.w;
        }
        // Load B tile (16 rows x 128 cols) as float4.
#pragma unroll
        for (int t = tid; t < 512; t += 256) {
            int r  = t >> 5;           // 0..15
            int c4 = (t & 31) << 2;    // 0..124
            *reinterpret_cast<float4*>(&Bs[r][c4]) =
                *reinterpret_cast<const float4*>(
                    &Bm[(size_t)(k0 + r) * N + col0 + c4]);
        }
        __syncthreads();

#pragma unroll
        for (int kk = 0; kk < 16; kk++) {
            float a[8], b[8];
            *reinterpret_cast<float4*>(a)     = *reinterpret_cast<const float4*>(&As[kk][ty * 8]);
            *reinterpret_cast<float4*>(a + 4) = *reinterpret_cast<const float4*>(&As[kk][ty * 8 + 4]);
            *reinterpret_cast<float4*>(b)     = *reinterpret_cast<const float4*>(&Bs[kk][tx * 8]);
            *reinterpret_cast<float4*>(b + 4) = *reinterpret_cast<const float4*>(&Bs[kk][tx * 8 + 4]);
#pragma unroll
            for (int i = 0; i < 8; i++)
#pragma unroll
                for (int j = 0; j < 8; j++)
                    acc[i][j] += a[i] * b[j];
        }
        __syncthreads();
    }

    // Epilogue with bias
#pragma unroll
    for (int i = 0; i < 8; i++) {
        const size_t r = (size_t)(row0 + ty * 8 + i);
#pragma unroll
        for (int j = 0; j < 8; j += 4) {
            const int c = col0 + tx * 8 + j;
            float4 v;
            v.x = acc[i][j + 0] + bias[c + 0];
            v.y = acc[i][j + 1] + bias[c + 1];
            v.z = acc[i][j + 2] + bias[c + 2];
            v.w = acc[i][j + 3] + bias[c + 3];
            *reinterpret_cast<float4*>(&Cm[r * N + c]) = v;
        }
    }
}

// ---------------------------------------------------------------------------
// Flash attention (fp32, causal). One block = one (b,h) x 64-query tile.
// 128 threads: ty(0..7) owns 8 queries, tx(0..15) owns 4 kv cols / 4 out dims.
// Online softmax with 16-lane shfl reductions. Causal early exit (kvb <= qb).
// Dynamic smem: Qt, Kt (d-major), Vs, Ps, each 64x68 floats = 69632 B.
// ---------------------------------------------------------------------------
#define AT_S 68   // padded row stride (keeps float4 alignment, dodges conflicts)

__global__ __launch_bounds__(128)
void attn_kernel(const float* __restrict__ qkv, float* __restrict__ att) {
    extern __shared__ __align__(16) float sm[];
    float* Qt = sm;                 // [d][q]  (transposed), scaled by 1/sqrt(HD)
    float* Kt = sm + 64 * AT_S;     // [d][j]  (transposed)
    float* Vs = sm + 2 * 64 * AT_S; // [j][d]  row-major
    float* Ps = sm + 3 * 64 * AT_S; // [q][j]  row-major

    const int tid = threadIdx.x;
    const int tx  = tid & 15;
    const int ty  = tid >> 4;
    const int qb  = blockIdx.x;          // 0..31 query tile
    const int bh  = blockIdx.y;          // 0..31
    const int b   = bh >> 4, h = bh & 15;

    const float* qbase = qkv + (size_t)b * T_ * NQKV_ + h * HD_;
    const float* kbase = qbase + C_;
    const float* vbase = qbase + 2 * C_;

    // Load Q tile (pre-scaled by 1/sqrt(64) = 0.125), store d-major.
    for (int idx = tid; idx < 64 * 64; idx += 128) {
        int r = idx >> 6, d = idx & 63;
        Qt[d * AT_S + r] = qbase[(size_t)(qb * 64 + r) * NQKV_ + d] * 0.125f;
    }

    float acc[8][4];
    float m[8], l[8];
#pragma unroll
    for (int i = 0; i < 8; i++) {
        m[i] = -1e30f; l[i] = 0.f;
#pragma unroll
        for (int j = 0; j < 4; j++) acc[i][j] = 0.f;
    }

    for (int kvb = 0; kvb <= qb; kvb++) {
        __syncthreads();   // protect Kt/Vs/Ps from previous iteration readers
        for (int idx = tid; idx < 64 * 64; idx += 128) {
            int r = idx >> 6, d = idx & 63;
            size_t goff = (size_t)(kvb * 64 + r) * NQKV_ + d;
            Kt[d * AT_S + r] = kbase[goff];
            Vs[r * AT_S + d] = vbase[goff];
        }
        __syncthreads();

        // S = (Q * scale) @ K^T  -> s[8][4]
        float s[8][4];
#pragma unroll
        for (int i = 0; i < 8; i++)
#pragma unroll
            for (int j = 0; j < 4; j++) s[i][j] = 0.f;

#pragma unroll 4
        for (int d = 0; d < 64; d++) {
            float4 kf = *reinterpret_cast<const float4*>(&Kt[d * AT_S + tx * 4]);
#pragma unroll
            for (int i = 0; i < 8; i++) {
                float qf = Qt[d * AT_S + ty * 8 + i];
                s[i][0] += qf * kf.x;
                s[i][1] += qf * kf.y;
                s[i][2] += qf * kf.z;
                s[i][3] += qf * kf.w;
            }
        }

        if (kvb == qb) {   // diagonal tile: causal mask (local indices suffice)
#pragma unroll
            for (int i = 0; i < 8; i++)
#pragma unroll
                for (int j = 0; j < 4; j++)
                    if (tx * 4 + j > ty * 8 + i) s[i][j] = -1e30f;
        }

        // Online softmax (row groups = 16 lanes sharing ty)
#pragma unroll
        for (int i = 0; i < 8; i++) {
            float mx = fmaxf(fmaxf(s[i][0], s[i][1]), fmaxf(s[i][2], s[i][3]));
            mx = fmaxf(mx, __shfl_xor_sync(0xffffffffu, mx, 1));
            mx = fmaxf(mx, __shfl_xor_sync(0xffffffffu, mx, 2));
            mx = fmaxf(mx, __shfl_xor_sync(0xffffffffu, mx, 4));
            mx = fmaxf(mx, __shfl_xor_sync(0xffffffffu, mx, 8));
            float mnew  = fmaxf(m[i], mx);
            float alpha = __expf(m[i] - mnew);
            float p0 = __expf(s[i][0] - mnew);
            float p1 = __expf(s[i][1] - mnew);
            float p2 = __expf(s[i][2] - mnew);
            float p3 = __expf(s[i][3] - mnew);
            float ls = p0 + p1 + p2 + p3;
            ls += __shfl_xor_sync(0xffffffffu, ls, 1);
            ls += __shfl_xor_sync(0xffffffffu, ls, 2);
            ls += __shfl_xor_sync(0xffffffffu, ls, 4);
            ls += __shfl_xor_sync(0xffffffffu, ls, 8);
            l[i] = l[i] * alpha + ls;
            m[i] = mnew;
#pragma unroll
            for (int j = 0; j < 4; j++) acc[i][j] *= alpha;
            float4 pv = make_float4(p0, p1, p2, p3);
            *reinterpret_cast<float4*>(&Ps[(ty * 8 + i) * AT_S + tx * 4]) = pv;
        }
        __syncthreads();   // Ps complete before PV

        // O += P @ V
#pragma unroll 2
        for (int j4 = 0; j4 < 64; j4 += 4) {
            float4 v0 = *reinterpret_cast<const float4*>(&Vs[(j4 + 0) * AT_S + tx * 4]);
            float4 v1 = *reinterpret_cast<const float4*>(&Vs[(j4 + 1) * AT_S + tx * 4]);
            float4 v2 = *reinterpret_cast<const float4*>(&Vs[(j4 + 2) * AT_S + tx * 4]);
            float4 v3 = *reinterpret_cast<const float4*>(&Vs[(j4 + 3) * AT_S + tx * 4]);
#pragma unroll
            for (int i = 0; i < 8; i++) {
                float4 p = *reinterpret_cast<const float4*>(&Ps[(ty * 8 + i) * AT_S + j4]);
                acc[i][0] += p.x * v0.x + p.y * v1.x + p.z * v2.x + p.w * v3.x;
                acc[i][1] += p.x * v0.y + p.y * v1.y + p.z * v2.y + p.w * v3.y;
                acc[i][2] += p.x * v0.z + p.y * v1.z + p.z * v2.z + p.w * v3.z;
                acc[i][3] += p.x * v0.w + p.y * v1.w + p.z * v2.w + p.w * v3.w;
            }
        }
    }

    // Epilogue: normalize and scatter to (B*T, C) at this head's column slice.
#pragma unroll
    for (int i = 0; i < 8; i++) {
        float inv = 1.f / l[i];
        float4 o = make_float4(acc[i][0] * inv, acc[i][1] * inv,
                               acc[i][2] * inv, acc[i][3] * inv);
        size_t row = (size_t)b * T_ + qb * 64 + ty * 8 + i;
        *reinterpret_cast<float4*>(&att[row * C_ + h * HD_ + tx * 4]) = o;
    }
}

// ---------------------------------------------------------------------------
// Launch
// ---------------------------------------------------------------------------
extern "C" void kernel_launch(void* const* d_in, const int* in_sizes, int n_in,
                              void* d_out, int out_size) {
    const float* x     = (const float*)d_in[0];
    const float* Wqkv  = (const float*)d_in[1];
    const float* bqkv  = (const float*)d_in[2];
    const float* Wproj = (const float*)d_in[3];
    const float* bproj = (const float*)d_in[4];
    float* out = (float*)d_out;

    float *qkv_ptr, *att_ptr;
    cudaGetSymbolAddress((void**)&qkv_ptr, g_qkv);
    cudaGetSymbolAddress((void**)&att_ptr, g_att);

    const int attn_smem = 4 * 64 * AT_S * sizeof(float);  // 69632 B
    cudaFuncSetAttribute(attn_kernel,
                         cudaFuncAttributeMaxDynamicSharedMemorySize, attn_smem);

    // 1) QKV GEMM: (4096 x 1024) @ (1024 x 3072) + bqkv
    dim3 g1(NQKV_ / 128, M_ / 128);   // 24 x 32
    sgemm_bias<<<g1, 256>>>(x, Wqkv, bqkv, qkv_ptr, M_, NQKV_, C_);

    // 2) Causal flash attention over the interleaved qkv buffer
    dim3 g2(T_ / 64, B_ * NH_);       // 32 x 32
    attn_kernel<<<g2, 128, attn_smem>>>(qkv_ptr, att_ptr);

    // 3) Output projection: (4096 x 1024) @ (1024 x 1024) + bproj
    dim3 g3(C_ / 128, M_ / 128);      // 8 x 32
    sgemm_bias<<<g3, 256>>>(att_ptr, Wproj, bproj, out, M_, C_, C_);
}

// round 3
// speedup vs baseline: 1.4796x; 1.4796x over previous
#include <cuda_runtime.h>
#include <cstdint>

// Problem constants
#define B_    2
#define T_    2048
#define C_    1024
#define NH_   16
#define HD_   64
#define M_    (B_ * T_)     // 4096 rows
#define NQKV_ (3 * C_)      // 3072

// Scratch (device globals: allocation-free)
__device__ float g_qkv[(size_t)M_ * NQKV_];   // (B*T, 3C)
__device__ float g_att[(size_t)M_ * C_];      // (B*T, C) attention output

// ---------------------------------------------------------------------------
// TF32 tensor-core GEMM + bias:  C[M,N] = A[M,K] @ B[K,N] + bias[N]
// 128x128x32 tiles, 256 threads (8 warps as 2x4), warp tile 64x32,
// mma.sync.aligned.m16n8k8.row.col.f32.tf32.tf32.f32.
// Smem layout [k][*] with stride 136 (== 8 mod 32) -> conflict-free fragment
// loads (bank = 8*t4 + g, all 32 lanes distinct). Inputs cvt.rna'd to tf32
// once on the gmem->smem path.
// ---------------------------------------------------------------------------
#define GS 136   // smem row stride (floats)

__device__ __forceinline__ uint32_t f2tf32(float f) {
    uint32_t u;
    asm volatile("cvt.rna.tf32.f32 %0, %1;" : "=r"(u) : "f"(f));
    return u;
}

__global__ __launch_bounds__(256, 2)
void gemm_tf32_bias(const float* __restrict__ A, const float* __restrict__ Bm,
                    const float* __restrict__ bias, float* __restrict__ Cm,
                    int M, int N, int K) {
    __shared__ __align__(16) uint32_t As[32][GS];   // [k][m] tf32 bits
    __shared__ __align__(16) uint32_t Bs[32][GS];   // [k][n] tf32 bits

    const int tid  = threadIdx.x;
    const int lane = tid & 31;
    const int warp = tid >> 5;
    const int wm   = warp >> 2;          // 0..1 -> m offset 64*wm
    const int wn   = warp & 3;           // 0..3 -> n offset 32*wn
    const int g    = lane >> 2;          // 0..7
    const int t4   = lane & 3;           // 0..3

    const int row0 = blockIdx.y * 128;
    const int col0 = blockIdx.x * 128;

    float acc[4][4][4];                  // [mt][nt][c0..c3]
#pragma unroll
    for (int mt = 0; mt < 4; mt++)
#pragma unroll
        for (int nt = 0; nt < 4; nt++)
#pragma unroll
            for (int c = 0; c < 4; c++) acc[mt][nt][c] = 0.f;

    for (int k0 = 0; k0 < K; k0 += 32) {
        __syncthreads();
        // A tile: 128 rows x 32 k, float4 along k, scatter into As[k][m]
#pragma unroll
        for (int t = tid; t < 1024; t += 256) {
            int m  = t >> 3;            // 0..127
            int k4 = (t & 7) << 2;      // 0,4,...,28
            float4 v = *reinterpret_cast<const float4*>(
                &A[(size_t)(row0 + m) * K + k0 + k4]);
            As[k4 + 0][m] = f2tf32(v.x);
            As[k4 + 1][m] = f2tf32(v.y);
            As[k4 + 2][m] = f2tf32(v.z);
            As[k4 + 3][m] = f2tf32(v.w);
        }
        // B tile: 32 k x 128 n, float4 along n, into Bs[k][n]
#pragma unroll
        for (int t = tid; t < 1024; t += 256) {
            int k  = t >> 5;            // 0..31
            int n4 = (t & 31) << 2;     // 0..124
            float4 v = *reinterpret_cast<const float4*>(
                &Bm[(size_t)(k0 + k) * N + col0 + n4]);
            uint4 u;
            u.x = f2tf32(v.x); u.y = f2tf32(v.y);
            u.z = f2tf32(v.z); u.w = f2tf32(v.w);
            *reinterpret_cast<uint4*>(&Bs[k][n4]) = u;
        }
        __syncthreads();

#pragma unroll
        for (int kk = 0; kk < 32; kk += 8) {
            uint32_t ra[4][4], rb[4][2];
            const int kA = kk + t4;
#pragma unroll
            for (int mt = 0; mt < 4; mt++) {
                int mb = wm * 64 + mt * 16 + g;
                ra[mt][0] = As[kA][mb];
                ra[mt][1] = As[kA][mb + 8];
                ra[mt][2] = As[kA + 4][mb];
                ra[mt][3] = As[kA + 4][mb + 8];
            }
#pragma unroll
            for (int nt = 0; nt < 4; nt++) {
                int nb = wn * 32 + nt * 8 + g;
                rb[nt][0] = Bs[kA][nb];
                rb[nt][1] = Bs[kA + 4][nb];
            }
#pragma unroll
            for (int mt = 0; mt < 4; mt++)
#pragma unroll
                for (int nt = 0; nt < 4; nt++) {
                    asm volatile(
                        "mma.sync.aligned.m16n8k8.row.col.f32.tf32.tf32.f32 "
                        "{%0,%1,%2,%3}, {%4,%5,%6,%7}, {%8,%9}, {%0,%1,%2,%3};"
                        : "+f"(acc[mt][nt][0]), "+f"(acc[mt][nt][1]),
                          "+f"(acc[mt][nt][2]), "+f"(acc[mt][nt][3])
                        : "r"(ra[mt][0]), "r"(ra[mt][1]),
                          "r"(ra[mt][2]), "r"(ra[mt][3]),
                          "r"(rb[nt][0]), "r"(rb[nt][1]));
                }
        }
    }

    // Epilogue with bias. c0=(g,2t4) c1=(g,2t4+1) c2=(g+8,2t4) c3=(g+8,2t4+1)
#pragma unroll
    for (int mt = 0; mt < 4; mt++) {
        const int rA = row0 + wm * 64 + mt * 16 + g;
        const int rB = rA + 8;
#pragma unroll
        for (int nt = 0; nt < 4; nt++) {
            const int c = col0 + wn * 32 + nt * 8 + 2 * t4;
            const float b0 = bias[c], b1 = bias[c + 1];
            float2 v0 = make_float2(acc[mt][nt][0] + b0, acc[mt][nt][1] + b1);
            float2 v1 = make_float2(acc[mt][nt][2] + b0, acc[mt][nt][3] + b1);
            *reinterpret_cast<float2*>(&Cm[(size_t)rA * N + c]) = v0;
            *reinterpret_cast<float2*>(&Cm[(size_t)rB * N + c]) = v1;
        }
    }
}

// ---------------------------------------------------------------------------
// Flash attention (fp32, causal). One block = one (b,h) x 64-query tile.
// (unchanged from round 1 — next optimization target)
// ---------------------------------------------------------------------------
#define AT_S 68

__global__ __launch_bounds__(128)
void attn_kernel(const float* __restrict__ qkv, float* __restrict__ att) {
    extern __shared__ __align__(16) float sm[];
    float* Qt = sm;                 // [d][q]  (transposed), scaled by 1/8
    float* Kt = sm + 64 * AT_S;     // [d][j]
    float* Vs = sm + 2 * 64 * AT_S; // [j][d]
    float* Ps = sm + 3 * 64 * AT_S; // [q][j]

    const int tid = threadIdx.x;
    const int tx  = tid & 15;
    const int ty  = tid >> 4;
    const int qb  = blockIdx.x;
    const int bh  = blockIdx.y;
    const int b   = bh >> 4, h = bh & 15;

    const float* qbase = qkv + (size_t)b * T_ * NQKV_ + h * HD_;
    const float* kbase = qbase + C_;
    const float* vbase = qbase + 2 * C_;

    for (int idx = tid; idx < 64 * 64; idx += 128) {
        int r = idx >> 6, d = idx & 63;
        Qt[d * AT_S + r] = qbase[(size_t)(qb * 64 + r) * NQKV_ + d] * 0.125f;
    }

    float acc[8][4];
    float m[8], l[8];
#pragma unroll
    for (int i = 0; i < 8; i++) {
        m[i] = -1e30f; l[i] = 0.f;
#pragma unroll
        for (int j = 0; j < 4; j++) acc[i][j] = 0.f;
    }

    for (int kvb = 0; kvb <= qb; kvb++) {
        __syncthreads();
        for (int idx = tid; idx < 64 * 64; idx += 128) {
            int r = idx >> 6, d = idx & 63;
            size_t goff = (size_t)(kvb * 64 + r) * NQKV_ + d;
            Kt[d * AT_S + r] = kbase[goff];
            Vs[r * AT_S + d] = vbase[goff];
        }
        __syncthreads();

        float s[8][4];
#pragma unroll
        for (int i = 0; i < 8; i++)
#pragma unroll
            for (int j = 0; j < 4; j++) s[i][j] = 0.f;

#pragma unroll 4
        for (int d = 0; d < 64; d++) {
            float4 kf = *reinterpret_cast<const float4*>(&Kt[d * AT_S + tx * 4]);
#pragma unroll
            for (int i = 0; i < 8; i++) {
                float qf = Qt[d * AT_S + ty * 8 + i];
                s[i][0] += qf * kf.x;
                s[i][1] += qf * kf.y;
                s[i][2] += qf * kf.z;
                s[i][3] += qf * kf.w;
            }
        }

        if (kvb == qb) {
#pragma unroll
            for (int i = 0; i < 8; i++)
#pragma unroll
                for (int j = 0; j < 4; j++)
                    if (tx * 4 + j > ty * 8 + i) s[i][j] = -1e30f;
        }

#pragma unroll
        for (int i = 0; i < 8; i++) {
            float mx = fmaxf(fmaxf(s[i][0], s[i][1]), fmaxf(s[i][2], s[i][3]));
            mx = fmaxf(mx, __shfl_xor_sync(0xffffffffu, mx, 1));
            mx = fmaxf(mx, __shfl_xor_sync(0xffffffffu, mx, 2));
            mx = fmaxf(mx, __shfl_xor_sync(0xffffffffu, mx, 4));
            mx = fmaxf(mx, __shfl_xor_sync(0xffffffffu, mx, 8));
            float mnew  = fmaxf(m[i], mx);
            float alpha = __expf(m[i] - mnew);
            float p0 = __expf(s[i][0] - mnew);
            float p1 = __expf(s[i][1] - mnew);
            float p2 = __expf(s[i][2] - mnew);
            float p3 = __expf(s[i][3] - mnew);
            float ls = p0 + p1 + p2 + p3;
            ls += __shfl_xor_sync(0xffffffffu, ls, 1);
            ls += __shfl_xor_sync(0xffffffffu, ls, 2);
            ls += __shfl_xor_sync(0xffffffffu, ls, 4);
            ls += __shfl_xor_sync(0xffffffffu, ls, 8);
            l[i] = l[i] * alpha + ls;
            m[i] = mnew;
#pragma unroll
            for (int j = 0; j < 4; j++) acc[i][j] *= alpha;
            float4 pv = make_float4(p0, p1, p2, p3);
            *reinterpret_cast<float4*>(&Ps[(ty * 8 + i) * AT_S + tx * 4]) = pv;
        }
        __syncthreads();

#pragma unroll 2
        for (int j4 = 0; j4 < 64; j4 += 4) {
            float4 v0 = *reinterpret_cast<const float4*>(&Vs[(j4 + 0) * AT_S + tx * 4]);
            float4 v1 = *reinterpret_cast<const float4*>(&Vs[(j4 + 1) * AT_S + tx * 4]);
            float4 v2 = *reinterpret_cast<const float4*>(&Vs[(j4 + 2) * AT_S + tx * 4]);
            float4 v3 = *reinterpret_cast<const float4*>(&Vs[(j4 + 3) * AT_S + tx * 4]);
#pragma unroll
            for (int i = 0; i < 8; i++) {
                float4 p = *reinterpret_cast<const float4*>(&Ps[(ty * 8 + i) * AT_S + j4]);
                acc[i][0] += p.x * v0.x + p.y * v1.x + p.z * v2.x + p.w * v3.x;
                acc[i][1] += p.x * v0.y + p.y * v1.y + p.z * v2.y + p.w * v3.y;
                acc[i][2] += p.x * v0.z + p.y * v1.z + p.z * v2.z + p.w * v3.z;
                acc[i][3] += p.x * v0.w + p.y * v1.w + p.z * v2.w + p.w * v3.w;
            }
        }
    }

#pragma unroll
    for (int i = 0; i < 8; i++) {
        float inv = 1.f / l[i];
        float4 o = make_float4(acc[i][0] * inv, acc[i][1] * inv,
                               acc[i][2] * inv, acc[i][3] * inv);
        size_t row = (size_t)b * T_ + qb * 64 + ty * 8 + i;
        *reinterpret_cast<float4*>(&att[row * C_ + h * HD_ + tx * 4]) = o;
    }
}

// ---------------------------------------------------------------------------
// Launch
// ---------------------------------------------------------------------------
extern "C" void kernel_launch(void* const* d_in, const int* in_sizes, int n_in,
                              void* d_out, int out_size) {
    const float* x     = (const float*)d_in[0];
    const float* Wqkv  = (const float*)d_in[1];
    const float* bqkv  = (const float*)d_in[2];
    const float* Wproj = (const float*)d_in[3];
    const float* bproj = (const float*)d_in[4];
    float* out = (float*)d_out;

    float *qkv_ptr, *att_ptr;
    cudaGetSymbolAddress((void**)&qkv_ptr, g_qkv);
    cudaGetSymbolAddress((void**)&att_ptr, g_att);

    const int attn_smem = 4 * 64 * AT_S * sizeof(float);  // 69632 B
    cudaFuncSetAttribute(attn_kernel,
                         cudaFuncAttributeMaxDynamicSharedMemorySize, attn_smem);

    // 1) QKV GEMM (tf32 tensor cores): (4096 x 1024) @ (1024 x 3072) + bqkv
    dim3 g1(NQKV_ / 128, M_ / 128);   // 24 x 32
    gemm_tf32_bias<<<g1, 256>>>(x, Wqkv, bqkv, qkv_ptr, M_, NQKV_, C_);

    // 2) Causal flash attention (fp32)
    dim3 g2(T_ / 64, B_ * NH_);       // 32 x 32
    attn_kernel<<<g2, 128, attn_smem>>>(qkv_ptr, att_ptr);

    // 3) Output projection (tf32): (4096 x 1024) @ (1024 x 1024) + bproj
    dim3 g3(C_ / 128, M_ / 128);      // 8 x 32
    gemm_tf32_bias<<<g3, 256>>>(att_ptr, Wproj, bproj, out, M_, C_, C_);
}

// round 4
// speedup vs baseline: 2.8243x; 1.9088x over previous
#include <cuda_runtime.h>
#include <cstdint>

// Problem constants
#define B_    2
#define T_    2048
#define C_    1024
#define NH_   16
#define HD_   64
#define M_    (B_ * T_)     // 4096
#define NQKV_ (3 * C_)      // 3072

// Scratch (device globals: allocation-free)
__device__ float g_qkv[(size_t)M_ * NQKV_];      // qkv activations (tf32 bits)
__device__ float g_att[(size_t)M_ * C_];         // attention out  (tf32 bits)
__device__ float g_xt [(size_t)M_ * C_];         // x   -> tf32
__device__ float g_wqkvt[(size_t)C_ * NQKV_];    // Wqkv -> tf32
__device__ float g_wprojt[(size_t)C_ * C_];      // Wproj -> tf32

// ---------------------------------------------------------------------------
// helpers
// ---------------------------------------------------------------------------
__device__ __forceinline__ uint32_t f2tf32(float f) {
    uint32_t u;
    asm volatile("cvt.rna.tf32.f32 %0, %1;" : "=r"(u) : "f"(f));
    return u;
}
__device__ __forceinline__ float ex2f(float x) {
    float y;
    asm volatile("ex2.approx.ftz.f32 %0, %1;" : "=f"(y) : "f"(x));
    return y;
}
__device__ __forceinline__ void cp16(uint32_t dsm, const void* src) {
    asm volatile("cp.async.ca.shared.global [%0], [%1], 16;" :: "r"(dsm), "l"(src));
}
#define CP_COMMIT() asm volatile("cp.async.commit_group;")
#define CP_WAIT1()  asm volatile("cp.async.wait_group 1;")

#define MMA_TF32(d, a0,a1,a2,a3, b0,b1)                                   \
    asm volatile("mma.sync.aligned.m16n8k8.row.col.f32.tf32.tf32.f32 "    \
        "{%0,%1,%2,%3}, {%4,%5,%6,%7}, {%8,%9}, {%0,%1,%2,%3};"           \
        : "+f"((d)[0]), "+f"((d)[1]), "+f"((d)[2]), "+f"((d)[3])          \
        : "r"(a0), "r"(a1), "r"(a2), "r"(a3), "r"(b0), "r"(b1))

// ---------------------------------------------------------------------------
// elementwise fp32 -> tf32(round-to-nearest) conversion
// ---------------------------------------------------------------------------
__global__ void cvt_kernel(const float4* __restrict__ in,
                           float4* __restrict__ out, int n4) {
    int i = blockIdx.x * blockDim.x + threadIdx.x;
    if (i < n4) {
        float4 v = in[i];
        float4 o;
        o.x = __uint_as_float(f2tf32(v.x));
        o.y = __uint_as_float(f2tf32(v.y));
        o.z = __uint_as_float(f2tf32(v.z));
        o.w = __uint_as_float(f2tf32(v.w));
        out[i] = o;
    }
}

// ---------------------------------------------------------------------------
// TF32 GEMM + bias, cp.async double-buffered. Operands pre-converted tf32.
// 128x128x32 tiles, 8 warps (2x4), warp tile 64x32.
// As[m][k] stride 36 (bank 4g+t4), Bs[k][n] stride 136 (bank 8t4+g): both
// conflict-free, both cp.async-compatible (16B contiguous in gmem order).
// ---------------------------------------------------------------------------
#define AST 36
#define BST 136
#define GEMM_SMEM ((2*128*AST + 2*32*BST) * 4)   // 71680 B

template<bool CVT_OUT>
__global__ __launch_bounds__(256, 2)
void gemm_db(const float* __restrict__ A, const float* __restrict__ Bm,
             const float* __restrict__ bias, float* __restrict__ Cm,
             int M, int N, int K) {
    extern __shared__ float smg[];
    float* As = smg;                 // [2][128][AST]
    float* Bs = smg + 2*128*AST;     // [2][32][BST]

    const int tid  = threadIdx.x;
    const int lane = tid & 31, warp = tid >> 5;
    const int wm = warp >> 2, wn = warp & 3;
    const int g  = lane >> 2, t4 = lane & 3;
    const int row0 = blockIdx.y * 128, col0 = blockIdx.x * 128;

    const uint32_t sA = (uint32_t)__cvta_generic_to_shared(As);
    const uint32_t sB = (uint32_t)__cvta_generic_to_shared(Bs);

    auto issue = [&](int kt) {
        const int buf = kt & 1;
#pragma unroll
        for (int i = 0; i < 4; i++) {
            int idx = tid + 256 * i;
            int r = idx >> 3, kc = (idx & 7) << 2;
            cp16(sA + (uint32_t)((buf*128 + r)*AST + kc) * 4,
                 &A[(size_t)(row0 + r) * K + kt*32 + kc]);
        }
#pragma unroll
        for (int i = 0; i < 4; i++) {
            int idx = tid + 256 * i;
            int kr = idx >> 5, n4 = (idx & 31) << 2;
            cp16(sB + (uint32_t)((buf*32 + kr)*BST + n4) * 4,
                 &Bm[(size_t)(kt*32 + kr) * N + col0 + n4]);
        }
    };

    float acc[4][4][4];
#pragma unroll
    for (int mt = 0; mt < 4; mt++)
#pragma unroll
        for (int nt = 0; nt < 4; nt++)
#pragma unroll
            for (int c = 0; c < 4; c++) acc[mt][nt][c] = 0.f;

    const int KT = K >> 5;
    issue(0); CP_COMMIT();

    for (int kt = 0; kt < KT; kt++) {
        const int buf = kt & 1;
        if (kt + 1 < KT) issue(kt + 1);
        CP_COMMIT();
        CP_WAIT1();
        __syncthreads();

        const float* Ab = As + buf*128*AST;
        const float* Bb = Bs + buf*32*BST;
#pragma unroll
        for (int kk = 0; kk < 32; kk += 8) {
            uint32_t ra[4][4], rb[4][2];
#pragma unroll
            for (int mt = 0; mt < 4; mt++) {
                const float* ap = Ab + (wm*64 + mt*16 + g)*AST + kk + t4;
                ra[mt][0] = __float_as_uint(ap[0]);
                ra[mt][1] = __float_as_uint(ap[8*AST]);
                ra[mt][2] = __float_as_uint(ap[4]);
                ra[mt][3] = __float_as_uint(ap[8*AST + 4]);
            }
#pragma unroll
            for (int nt = 0; nt < 4; nt++) {
                const float* bp = Bb + (kk + t4)*BST + wn*32 + nt*8 + g;
                rb[nt][0] = __float_as_uint(bp[0]);
                rb[nt][1] = __float_as_uint(bp[4*BST]);
            }
#pragma unroll
            for (int mt = 0; mt < 4; mt++)
#pragma unroll
                for (int nt = 0; nt < 4; nt++)
                    MMA_TF32(acc[mt][nt], ra[mt][0], ra[mt][1], ra[mt][2],
                             ra[mt][3], rb[nt][0], rb[nt][1]);
        }
        __syncthreads();
    }

    // epilogue: + bias, optional tf32 re-round of the output
#pragma unroll
    for (int mt = 0; mt < 4; mt++) {
        const int rA = row0 + wm*64 + mt*16 + g;
        const int rB = rA + 8;
#pragma unroll
        for (int nt = 0; nt < 4; nt++) {
            const int c = col0 + wn*32 + nt*8 + 2*t4;
            const float b0 = bias[c], b1 = bias[c + 1];
            float v0 = acc[mt][nt][0] + b0, v1 = acc[mt][nt][1] + b1;
            float v2 = acc[mt][nt][2] + b0, v3 = acc[mt][nt][3] + b1;
            if (CVT_OUT) {
                v0 = __uint_as_float(f2tf32(v0));
                v1 = __uint_as_float(f2tf32(v1));
                v2 = __uint_as_float(f2tf32(v2));
                v3 = __uint_as_float(f2tf32(v3));
            }
            *reinterpret_cast<float2*>(&Cm[(size_t)rA * N + c]) = make_float2(v0, v1);
            *reinterpret_cast<float2*>(&Cm[(size_t)rB * N + c]) = make_float2(v2, v3);
        }
    }
}

// ---------------------------------------------------------------------------
// Tensor-core flash attention (tf32 mma, fp32 accum, exp2-domain softmax).
// Block = 128 queries x one (b,h). 8 warps x 16 rows (row-exclusive).
// KV tiles of 64. All fragment LDS conflict-free by stride choice; V's
// natural [j][d] layout is already the PV B-fragment layout.
// ---------------------------------------------------------------------------
#define QS_ST 68
#define KS_ST 68
#define VS_ST 72
#define PS_ST 68
#define ATTN_SMEM ((128*QS_ST + 64*KS_ST + 64*VS_ST + 128*PS_ST) * 4)  // 105472

#define MASKVAL (-6e30f)
#define MINIT   (-1e30f)

__global__ __launch_bounds__(256, 2)
void attn_tc(const float* __restrict__ qkv, float* __restrict__ att) {
    extern __shared__ float sm[];
    float* Qs = sm;                    // [128][QS_ST]
    float* Ks = Qs + 128*QS_ST;        // [64][KS_ST]
    float* Vs = Ks + 64*KS_ST;         // [64][VS_ST]
    float* Ps = Vs + 64*VS_ST;         // [128][PS_ST]

    const int tid  = threadIdx.x;
    const int lane = tid & 31, warp = tid >> 5;
    const int g = lane >> 2, t4 = lane & 3;
    const int qb = blockIdx.x, bh = blockIdx.y;
    const int b = bh >> 4, h = bh & 15;
    const int m0 = qb * 128;
    const int rb = warp * 16;

    const float* qbase = qkv + ((size_t)b*T_ + m0)*NQKV_ + h*HD_;
    const float* kbase = qkv + (size_t)b*T_*NQKV_ + h*HD_ + C_;
    const float* vbase = kbase + C_;

    // Q tile: scale by (1/8)*log2(e), re-round to tf32, store [q][d]
    const float qscale = 0.125f * 1.44269504088896340736f;
    for (int idx = tid; idx < 128*16; idx += 256) {
        int r = idx >> 4, d4 = (idx & 15) << 2;
        float4 v = *reinterpret_cast<const float4*>(&qbase[(size_t)r*NQKV_ + d4]);
        float* q = &Qs[r*QS_ST + d4];
        q[0] = __uint_as_float(f2tf32(v.x * qscale));
        q[1] = __uint_as_float(f2tf32(v.y * qscale));
        q[2] = __uint_as_float(f2tf32(v.z * qscale));
        q[3] = __uint_as_float(f2tf32(v.w * qscale));
    }

    float o[8][4];
    float mrow[2] = {MINIT, MINIT}, lrow[2] = {0.f, 0.f};
#pragma unroll
    for (int nt = 0; nt < 8; nt++)
#pragma unroll
        for (int c = 0; c < 4; c++) o[nt][c] = 0.f;

    const int nkv = 2*qb + 2;
    for (int kvb = 0; kvb < nkv; kvb++) {
        const int jb = kvb * 64;
        __syncthreads();   // previous tile fully consumed (also covers Q store)
        for (int idx = tid; idx < 64*16; idx += 256) {
            int j = idx >> 4, d4 = (idx & 15) << 2;
            float4 kf = *reinterpret_cast<const float4*>(&kbase[(size_t)(jb+j)*NQKV_ + d4]);
            float4 vf = *reinterpret_cast<const float4*>(&vbase[(size_t)(jb+j)*NQKV_ + d4]);
            *reinterpret_cast<float4*>(&Ks[j*KS_ST + d4]) = kf;
            *reinterpret_cast<float4*>(&Vs[j*VS_ST + d4]) = vf;
        }
        __syncthreads();

        if (jb > m0 + rb + 15) continue;   // warp fully above the diagonal

        // ---- S = Q' @ K^T ----
        float s[8][4];
#pragma unroll
        for (int nt = 0; nt < 8; nt++)
#pragma unroll
            for (int c = 0; c < 4; c++) s[nt][c] = 0.f;

#pragma unroll
        for (int kk = 0; kk < 64; kk += 8) {
            const float* ap = &Qs[(rb + g)*QS_ST + kk + t4];
            uint32_t a0 = __float_as_uint(ap[0]);
            uint32_t a1 = __float_as_uint(ap[8*QS_ST]);
            uint32_t a2 = __float_as_uint(ap[4]);
            uint32_t a3 = __float_as_uint(ap[8*QS_ST + 4]);
#pragma unroll
            for (int nt = 0; nt < 8; nt++) {
                const float* bp = &Ks[(nt*8 + g)*KS_ST + kk + t4];
                uint32_t b0 = __float_as_uint(bp[0]);
                uint32_t b1 = __float_as_uint(bp[4]);
                MMA_TF32(s[nt], a0, a1, a2, a3, b0, b1);
            }
        }

        // ---- causal mask (diagonal-crossing tiles only) ----
        if (jb + 63 > m0 + rb) {
            const int r0 = m0 + rb + g, r1 = r0 + 8;
#pragma unroll
            for (int nt = 0; nt < 8; nt++) {
                int cb = jb + nt*8 + 2*t4;
                if (cb     > r0) s[nt][0] = MASKVAL;
                if (cb + 1 > r0) s[nt][1] = MASKVAL;
                if (cb     > r1) s[nt][2] = MASKVAL;
                if (cb + 1 > r1) s[nt][3] = MASKVAL;
            }
        }

        // ---- online softmax (exp2 domain); rows rb+g and rb+g+8 ----
        float mx0 = MINIT, mx1 = MINIT;
#pragma unroll
        for (int nt = 0; nt < 8; nt++) {
            mx0 = fmaxf(mx0, fmaxf(s[nt][0], s[nt][1]));
            mx1 = fmaxf(mx1, fmaxf(s[nt][2], s[nt][3]));
        }
        mx0 = fmaxf(mx0, __shfl_xor_sync(0xffffffffu, mx0, 1));
        mx0 = fmaxf(mx0, __shfl_xor_sync(0xffffffffu, mx0, 2));
        mx1 = fmaxf(mx1, __shfl_xor_sync(0xffffffffu, mx1, 1));
        mx1 = fmaxf(mx1, __shfl_xor_sync(0xffffffffu, mx1, 2));
        const float mn0 = fmaxf(mrow[0], mx0), mn1 = fmaxf(mrow[1], mx1);
        const float al0 = ex2f(mrow[0] - mn0), al1 = ex2f(mrow[1] - mn1);
        mrow[0] = mn0; mrow[1] = mn1;

        float ls0 = 0.f, ls1 = 0.f;
#pragma unroll
        for (int nt = 0; nt < 8; nt++) {
            s[nt][0] = ex2f(s[nt][0] - mn0);
            s[nt][1] = ex2f(s[nt][1] - mn0);
            s[nt][2] = ex2f(s[nt][2] - mn1);
            s[nt][3] = ex2f(s[nt][3] - mn1);
            ls0 += s[nt][0] + s[nt][1];
            ls1 += s[nt][2] + s[nt][3];
            o[nt][0] *= al0; o[nt][1] *= al0;
            o[nt][2] *= al1; o[nt][3] *= al1;
            // stage P (tf32 bits) for the PV mma
            float* p0 = &Ps[(rb + g)*PS_ST + nt*8 + 2*t4];
            float* p1 = &Ps[(rb + g + 8)*PS_ST + nt*8 + 2*t4];
            *reinterpret_cast<float2*>(p0) =
                make_float2(__uint_as_float(f2tf32(s[nt][0])),
                            __uint_as_float(f2tf32(s[nt][1])));
            *reinterpret_cast<float2*>(p1) =
                make_float2(__uint_as_float(f2tf32(s[nt][2])),
                            __uint_as_float(f2tf32(s[nt][3])));
        }
        ls0 += __shfl_xor_sync(0xffffffffu, ls0, 1);
        ls0 += __shfl_xor_sync(0xffffffffu, ls0, 2);
        ls1 += __shfl_xor_sync(0xffffffffu, ls1, 1);
        ls1 += __shfl_xor_sync(0xffffffffu, ls1, 2);
        lrow[0] = lrow[0]*al0 + ls0;
        lrow[1] = lrow[1]*al1 + ls1;

        __syncwarp();   // P visible to all lanes of this warp

        // ---- O += P @ V ----
#pragma unroll
        for (int kk = 0; kk < 64; kk += 8) {
            const float* ap = &Ps[(rb + g)*PS_ST + kk + t4];
            uint32_t a0 = __float_as_uint(ap[0]);
            uint32_t a1 = __float_as_uint(ap[8*PS_ST]);
            uint32_t a2 = __float_as_uint(ap[4]);
            uint32_t a3 = __float_as_uint(ap[8*PS_ST + 4]);
#pragma unroll
            for (int nt = 0; nt < 8; nt++) {
                const float* bp = &Vs[(kk + t4)*VS_ST + nt*8 + g];
                uint32_t b0 = __float_as_uint(bp[0]);
                uint32_t b1 = __float_as_uint(bp[4*VS_ST]);
                MMA_TF32(o[nt], a0, a1, a2, a3, b0, b1);
            }
        }
    }

    // ---- epilogue: normalize, write tf32 bits (feeds proj GEMM) ----
    const float inv0 = 1.0f / lrow[0], inv1 = 1.0f / lrow[1];
    const size_t r0 = (size_t)b*T_ + m0 + rb + g;
    const size_t r1 = r0 + 8;
#pragma unroll
    for (int nt = 0; nt < 8; nt++) {
        const int c = h*HD_ + nt*8 + 2*t4;
        *reinterpret_cast<float2*>(&att[r0*C_ + c]) =
            make_float2(__uint_as_float(f2tf32(o[nt][0] * inv0)),
                        __uint_as_float(f2tf32(o[nt][1] * inv0)));
        *reinterpret_cast<float2*>(&att[r1*C_ + c]) =
            make_float2(__uint_as_float(f2tf32(o[nt][2] * inv1)),
                        __uint_as_float(f2tf32(o[nt][3] * inv1)));
    }
}

// ---------------------------------------------------------------------------
// Launch
// ---------------------------------------------------------------------------
extern "C" void kernel_launch(void* const* d_in, const int* in_sizes, int n_in,
                              void* d_out, int out_size) {
    const float* x     = (const float*)d_in[0];
    const float* Wqkv  = (const float*)d_in[1];
    const float* bqkv  = (const float*)d_in[2];
    const float* Wproj = (const float*)d_in[3];
    const float* bproj = (const float*)d_in[4];
    float* out = (float*)d_out;

    float *qkv_p, *att_p, *xt_p, *wq_p, *wp_p;
    cudaGetSymbolAddress((void**)&qkv_p, g_qkv);
    cudaGetSymbolAddress((void**)&att_p, g_att);
    cudaGetSymbolAddress((void**)&xt_p,  g_xt);
    cudaGetSymbolAddress((void**)&wq_p,  g_wqkvt);
    cudaGetSymbolAddress((void**)&wp_p,  g_wprojt);

    cudaFuncSetAttribute(gemm_db<true>,
                         cudaFuncAttributeMaxDynamicSharedMemorySize, GEMM_SMEM);
    cudaFuncSetAttribute(gemm_db<false>,
                         cudaFuncAttributeMaxDynamicSharedMemorySize, GEMM_SMEM);
    cudaFuncSetAttribute(attn_tc,
                         cudaFuncAttributeMaxDynamicSharedMemorySize, ATTN_SMEM);

    // 0) pre-convert operands to tf32
    {
        int n4x = M_*C_/4, n4q = C_*NQKV_/4, n4p = C_*C_/4;
        cvt_kernel<<<n4x/256, 256>>>((const float4*)x,     (float4*)xt_p, n4x);
        cvt_kernel<<<n4q/256, 256>>>((const float4*)Wqkv,  (float4*)wq_p, n4q);
        cvt_kernel<<<n4p/256, 256>>>((const float4*)Wproj, (float4*)wp_p, n4p);
    }

    // 1) QKV GEMM (output kept in tf32 bits for attention)
    dim3 g1(NQKV_/128, M_/128);
    gemm_db<true><<<g1, 256, GEMM_SMEM>>>(xt_p, wq_p, bqkv, qkv_p, M_, NQKV_, C_);

    // 2) Flash attention (tensor cores), writes tf32 bits
    dim3 g2(T_/128, B_*NH_);
    attn_tc<<<g2, 256, ATTN_SMEM>>>(qkv_p, att_p);

    // 3) Output projection (fp32 output)
    dim3 g3(C_/128, M_/128);
    gemm_db<false><<<g3, 256, GEMM_SMEM>>>(att_p, wp_p, bproj, out, M_, C_, C_);
}

// round 5
// speedup vs baseline: 2.8250x; 1.0003x over previous
#include <cuda_runtime.h>
#include <cstdint>

// Problem constants
#define B_    2
#define T_    2048
#define C_    1024
#define NH_   16
#define HD_   64
#define M_    (B_ * T_)     // 4096
#define NQKV_ (3 * C_)      // 3072

// Scratch (device globals: allocation-free)
__device__ float g_qkv[(size_t)M_ * NQKV_];      // qkv activations (tf32 bits)
__device__ float g_att[(size_t)M_ * C_];         // attention out  (tf32 bits)
__device__ float g_xt [(size_t)M_ * C_];         // x   -> tf32
__device__ float g_wqkvt[(size_t)C_ * NQKV_];    // Wqkv -> tf32
__device__ float g_wprojt[(size_t)C_ * C_];      // Wproj -> tf32

// ---------------------------------------------------------------------------
// helpers
// ---------------------------------------------------------------------------
__device__ __forceinline__ uint32_t f2tf32(float f) {
    uint32_t u;
    asm volatile("cvt.rna.tf32.f32 %0, %1;" : "=r"(u) : "f"(f));
    return u;
}
__device__ __forceinline__ float ex2f(float x) {
    float y;
    asm volatile("ex2.approx.ftz.f32 %0, %1;" : "=f"(y) : "f"(x));
    return y;
}
__device__ __forceinline__ void cp16(uint32_t dsm, const void* src) {
    asm volatile("cp.async.ca.shared.global [%0], [%1], 16;" :: "r"(dsm), "l"(src));
}
#define CP_COMMIT() asm volatile("cp.async.commit_group;")
#define CP_WAIT1()  asm volatile("cp.async.wait_group 1;")
#define CP_WAIT0()  asm volatile("cp.async.wait_group 0;")

#define MMA_TF32(d, a0,a1,a2,a3, b0,b1)                                   \
    asm volatile("mma.sync.aligned.m16n8k8.row.col.f32.tf32.tf32.f32 "    \
        "{%0,%1,%2,%3}, {%4,%5,%6,%7}, {%8,%9}, {%0,%1,%2,%3};"           \
        : "+f"((d)[0]), "+f"((d)[1]), "+f"((d)[2]), "+f"((d)[3])          \
        : "r"(a0), "r"(a1), "r"(a2), "r"(a3), "r"(b0), "r"(b1))

// ---------------------------------------------------------------------------
// elementwise fp32 -> tf32(round-to-nearest) conversion
// ---------------------------------------------------------------------------
__global__ void cvt_kernel(const float4* __restrict__ in,
                           float4* __restrict__ out, int n4) {
    int i = blockIdx.x * blockDim.x + threadIdx.x;
    if (i < n4) {
        float4 v = in[i];
        float4 o;
        o.x = __uint_as_float(f2tf32(v.x));
        o.y = __uint_as_float(f2tf32(v.y));
        o.z = __uint_as_float(f2tf32(v.z));
        o.w = __uint_as_float(f2tf32(v.w));
        out[i] = o;
    }
}

// ---------------------------------------------------------------------------
// TF32 GEMM + bias, 3-stage cp.async pipeline + A-fragment register double
// buffer. 128x128x32 tiles, 8 warps (2x4), warp tile 64x32.
// As[m][k] stride 36 (bank 4g+t4), Bs[k][n] stride 136 (bank 8t4+g).
// ---------------------------------------------------------------------------
#define AST 36
#define BST 136
#define STG_A (128 * AST)
#define STG_B (32 * BST)
#define NSTAGE 3
#define GEMM_SMEM (NSTAGE * (STG_A + STG_B) * 4)   // 107520 B

template<bool CVT_OUT>
__global__ __launch_bounds__(256, 2)
void gemm_db(const float* __restrict__ A, const float* __restrict__ Bm,
             const float* __restrict__ bias, float* __restrict__ Cm,
             int M, int N, int K) {
    extern __shared__ float smg[];

    const int tid  = threadIdx.x;
    const int lane = tid & 31, warp = tid >> 5;
    const int wm = warp >> 2, wn = warp & 3;
    const int g  = lane >> 2, t4 = lane & 3;
    const int row0 = blockIdx.y * 128, col0 = blockIdx.x * 128;

    const uint32_t sbase = (uint32_t)__cvta_generic_to_shared(smg);

    auto issue = [&](int kt, int stg) {
        const uint32_t sA = sbase + (uint32_t)(stg * (STG_A + STG_B)) * 4;
        const uint32_t sB = sA + (uint32_t)STG_A * 4;
#pragma unroll
        for (int i = 0; i < 4; i++) {
            int idx = tid + 256 * i;
            int r = idx >> 3, kc = (idx & 7) << 2;
            cp16(sA + (uint32_t)(r * AST + kc) * 4,
                 &A[(size_t)(row0 + r) * K + kt * 32 + kc]);
        }
#pragma unroll
        for (int i = 0; i < 4; i++) {
            int idx = tid + 256 * i;
            int kr = idx >> 5, n4 = (idx & 31) << 2;
            cp16(sB + (uint32_t)(kr * BST + n4) * 4,
                 &Bm[(size_t)(kt * 32 + kr) * N + col0 + n4]);
        }
    };

    float acc[4][4][4];
#pragma unroll
    for (int mt = 0; mt < 4; mt++)
#pragma unroll
        for (int nt = 0; nt < 4; nt++)
#pragma unroll
            for (int c = 0; c < 4; c++) acc[mt][nt][c] = 0.f;

    const int KT = K >> 5;
    issue(0, 0); CP_COMMIT();
    issue(1, 1); CP_COMMIT();

    int s_cur = 0;
    for (int kt = 0; kt < KT; kt++) {
        if (kt + 1 < KT) { CP_WAIT1(); } else { CP_WAIT0(); }
        __syncthreads();
        if (kt + 2 < KT) {
            int s2 = s_cur + 2; if (s2 >= NSTAGE) s2 -= NSTAGE;
            issue(kt + 2, s2); CP_COMMIT();
        }

        const float* Ab = smg + s_cur * (STG_A + STG_B);
        const float* Bb = Ab + STG_A;

        uint32_t ra[2][4][4], rb[4][2];
        // prime A fragments for kk=0
#pragma unroll
        for (int mt = 0; mt < 4; mt++) {
            const float* ap = Ab + (wm*64 + mt*16 + g)*AST + t4;
            ra[0][mt][0] = __float_as_uint(ap[0]);
            ra[0][mt][1] = __float_as_uint(ap[8*AST]);
            ra[0][mt][2] = __float_as_uint(ap[4]);
            ra[0][mt][3] = __float_as_uint(ap[8*AST + 4]);
        }
#pragma unroll
        for (int kki = 0; kki < 4; kki++) {
            const int kk = kki * 8;
            const int cur = kki & 1, nxt = cur ^ 1;
            if (kki < 3) {
#pragma unroll
                for (int mt = 0; mt < 4; mt++) {
                    const float* ap = Ab + (wm*64 + mt*16 + g)*AST + kk + 8 + t4;
                    ra[nxt][mt][0] = __float_as_uint(ap[0]);
                    ra[nxt][mt][1] = __float_as_uint(ap[8*AST]);
                    ra[nxt][mt][2] = __float_as_uint(ap[4]);
                    ra[nxt][mt][3] = __float_as_uint(ap[8*AST + 4]);
                }
            }
#pragma unroll
            for (int nt = 0; nt < 4; nt++) {
                const float* bp = Bb + (kk + t4)*BST + wn*32 + nt*8 + g;
                rb[nt][0] = __float_as_uint(bp[0]);
                rb[nt][1] = __float_as_uint(bp[4*BST]);
            }
#pragma unroll
            for (int mt = 0; mt < 4; mt++)
#pragma unroll
                for (int nt = 0; nt < 4; nt++)
                    MMA_TF32(acc[mt][nt], ra[cur][mt][0], ra[cur][mt][1],
                             ra[cur][mt][2], ra[cur][mt][3],
                             rb[nt][0], rb[nt][1]);
        }
        s_cur = (s_cur + 1 == NSTAGE) ? 0 : s_cur + 1;
    }

    // epilogue: + bias, optional tf32 re-round of the output
#pragma unroll
    for (int mt = 0; mt < 4; mt++) {
        const int rA = row0 + wm*64 + mt*16 + g;
        const int rB = rA + 8;
#pragma unroll
        for (int nt = 0; nt < 4; nt++) {
            const int c = col0 + wn*32 + nt*8 + 2*t4;
            const float b0 = bias[c], b1 = bias[c + 1];
            float v0 = acc[mt][nt][0] + b0, v1 = acc[mt][nt][1] + b1;
            float v2 = acc[mt][nt][2] + b0, v3 = acc[mt][nt][3] + b1;
            if (CVT_OUT) {
                v0 = __uint_as_float(f2tf32(v0));
                v1 = __uint_as_float(f2tf32(v1));
                v2 = __uint_as_float(f2tf32(v2));
                v3 = __uint_as_float(f2tf32(v3));
            }
            *reinterpret_cast<float2*>(&Cm[(size_t)rA * N + c]) = make_float2(v0, v1);
            *reinterpret_cast<float2*>(&Cm[(size_t)rB * N + c]) = make_float2(v2, v3);
        }
    }
}

// ---------------------------------------------------------------------------
// Tensor-core flash attention, cp.async double-buffered K/V tiles.
// Block = 128 queries x one (b,h). 8 warps x 16 rows (row-exclusive).
// Heavy query-tiles scheduled first (qb reversed vs blockIdx).
// ---------------------------------------------------------------------------
#define QS_ST 68
#define KS_ST 68
#define VS_ST 72
#define KV_TILE (64 * KS_ST + 64 * VS_ST)   // floats per K+V stage
#define ATTN_SMEM ((128*QS_ST + 2*KV_TILE + 128*PS_ST) * 4)
#define PS_ST 68

#define MASKVAL (-6e30f)
#define MINIT   (-1e30f)

__global__ __launch_bounds__(256, 1)
void attn_tc(const float* __restrict__ qkv, float* __restrict__ att) {
    extern __shared__ float sm[];
    float* Qs  = sm;                        // [128][QS_ST]
    float* KV0 = Qs + 128*QS_ST;            // 2 stages of K[64][KS_ST] + V[64][VS_ST]
    float* Ps  = KV0 + 2*KV_TILE;           // [128][PS_ST]

    const int tid  = threadIdx.x;
    const int lane = tid & 31, warp = tid >> 5;
    const int g = lane >> 2, t4 = lane & 3;
    const int qb = gridDim.x - 1 - blockIdx.x;   // heavy tiles first
    const int bh = blockIdx.y;
    const int b = bh >> 4, h = bh & 15;
    const int m0 = qb * 128;
    const int rb = warp * 16;

    const float* qbase = qkv + ((size_t)b*T_ + m0)*NQKV_ + h*HD_;
    const float* kbase = qkv + (size_t)b*T_*NQKV_ + h*HD_ + C_;
    const float* vbase = kbase + C_;

    const uint32_t skv = (uint32_t)__cvta_generic_to_shared(KV0);

    auto issue = [&](int kvb) {
        const uint32_t sK = skv + (uint32_t)((kvb & 1) * KV_TILE) * 4;
        const uint32_t sV = sK + (uint32_t)(64 * KS_ST) * 4;
        const int jb = kvb * 64;
#pragma unroll
        for (int i = 0; i < 4; i++) {
            int idx = tid + 256 * i;
            int j = idx >> 4, d4 = (idx & 15) << 2;
            cp16(sK + (uint32_t)(j*KS_ST + d4) * 4, &kbase[(size_t)(jb+j)*NQKV_ + d4]);
        }
#pragma unroll
        for (int i = 0; i < 4; i++) {
            int idx = tid + 256 * i;
            int j = idx >> 4, d4 = (idx & 15) << 2;
            cp16(sV + (uint32_t)(j*VS_ST + d4) * 4, &vbase[(size_t)(jb+j)*NQKV_ + d4]);
        }
    };

    issue(0); CP_COMMIT();

    // Q tile: scale by (1/8)*log2(e), re-round to tf32, store [q][d]
    const float qscale = 0.125f * 1.44269504088896340736f;
    for (int idx = tid; idx < 128*16; idx += 256) {
        int r = idx >> 4, d4 = (idx & 15) << 2;
        float4 v = *reinterpret_cast<const float4*>(&qbase[(size_t)r*NQKV_ + d4]);
        float* q = &Qs[r*QS_ST + d4];
        q[0] = __uint_as_float(f2tf32(v.x * qscale));
        q[1] = __uint_as_float(f2tf32(v.y * qscale));
        q[2] = __uint_as_float(f2tf32(v.z * qscale));
        q[3] = __uint_as_float(f2tf32(v.w * qscale));
    }

    float o[8][4];
    float mrow[2] = {MINIT, MINIT}, lrow[2] = {0.f, 0.f};
#pragma unroll
    for (int nt = 0; nt < 8; nt++)
#pragma unroll
        for (int c = 0; c < 4; c++) o[nt][c] = 0.f;

    const int nkv = 2*qb + 2;
    for (int kvb = 0; kvb < nkv; kvb++) {
        const int jb = kvb * 64;
        CP_WAIT0();          // this tile's K/V landed (per-thread)
        __syncthreads();     // visible to all; all warps done with prev buffer
        if (kvb + 1 < nkv) { issue(kvb + 1); CP_COMMIT(); }

        const float* Ks = KV0 + (kvb & 1) * KV_TILE;
        const float* Vs = Ks + 64 * KS_ST;

        if (jb > m0 + rb + 15) continue;   // warp fully above the diagonal

        // ---- S = Q' @ K^T ----
        float s[8][4];
#pragma unroll
        for (int nt = 0; nt < 8; nt++)
#pragma unroll
            for (int c = 0; c < 4; c++) s[nt][c] = 0.f;

#pragma unroll
        for (int kk = 0; kk < 64; kk += 8) {
            const float* ap = &Qs[(rb + g)*QS_ST + kk + t4];
            uint32_t a0 = __float_as_uint(ap[0]);
            uint32_t a1 = __float_as_uint(ap[8*QS_ST]);
            uint32_t a2 = __float_as_uint(ap[4]);
            uint32_t a3 = __float_as_uint(ap[8*QS_ST + 4]);
#pragma unroll
            for (int nt = 0; nt < 8; nt++) {
                const float* bp = &Ks[(nt*8 + g)*KS_ST + kk + t4];
                uint32_t b0 = __float_as_uint(bp[0]);
                uint32_t b1 = __float_as_uint(bp[4]);
                MMA_TF32(s[nt], a0, a1, a2, a3, b0, b1);
            }
        }

        // ---- causal mask (diagonal-crossing tiles only) ----
        if (jb + 63 > m0 + rb) {
            const int r0 = m0 + rb + g, r1 = r0 + 8;
#pragma unroll
            for (int nt = 0; nt < 8; nt++) {
                int cb = jb + nt*8 + 2*t4;
                if (cb     > r0) s[nt][0] = MASKVAL;
                if (cb + 1 > r0) s[nt][1] = MASKVAL;
                if (cb     > r1) s[nt][2] = MASKVAL;
                if (cb + 1 > r1) s[nt][3] = MASKVAL;
            }
        }

        // ---- online softmax (exp2 domain); rows rb+g and rb+g+8 ----
        float mx0 = MINIT, mx1 = MINIT;
#pragma unroll
        for (int nt = 0; nt < 8; nt++) {
            mx0 = fmaxf(mx0, fmaxf(s[nt][0], s[nt][1]));
            mx1 = fmaxf(mx1, fmaxf(s[nt][2], s[nt][3]));
        }
        mx0 = fmaxf(mx0, __shfl_xor_sync(0xffffffffu, mx0, 1));
        mx0 = fmaxf(mx0, __shfl_xor_sync(0xffffffffu, mx0, 2));
        mx1 = fmaxf(mx1, __shfl_xor_sync(0xffffffffu, mx1, 1));
        mx1 = fmaxf(mx1, __shfl_xor_sync(0xffffffffu, mx1, 2));
        const float mn0 = fmaxf(mrow[0], mx0), mn1 = fmaxf(mrow[1], mx1);
        const float al0 = ex2f(mrow[0] - mn0), al1 = ex2f(mrow[1] - mn1);
        mrow[0] = mn0; mrow[1] = mn1;

        float ls0 = 0.f, ls1 = 0.f;
#pragma unroll
        for (int nt = 0; nt < 8; nt++) {
            s[nt][0] = ex2f(s[nt][0] - mn0);
            s[nt][1] = ex2f(s[nt][1] - mn0);
            s[nt][2] = ex2f(s[nt][2] - mn1);
            s[nt][3] = ex2f(s[nt][3] - mn1);
            ls0 += s[nt][0] + s[nt][1];
            ls1 += s[nt][2] + s[nt][3];
            o[nt][0] *= al0; o[nt][1] *= al0;
            o[nt][2] *= al1; o[nt][3] *= al1;
            float* p0 = &Ps[(rb + g)*PS_ST + nt*8 + 2*t4];
            float* p1 = &Ps[(rb + g + 8)*PS_ST + nt*8 + 2*t4];
            *reinterpret_cast<float2*>(p0) =
                make_float2(__uint_as_float(f2tf32(s[nt][0])),
                            __uint_as_float(f2tf32(s[nt][1])));
            *reinterpret_cast<float2*>(p1) =
                make_float2(__uint_as_float(f2tf32(s[nt][2])),
                            __uint_as_float(f2tf32(s[nt][3])));
        }
        ls0 += __shfl_xor_sync(0xffffffffu, ls0, 1);
        ls0 += __shfl_xor_sync(0xffffffffu, ls0, 2);
        ls1 += __shfl_xor_sync(0xffffffffu, ls1, 1);
        ls1 += __shfl_xor_sync(0xffffffffu, ls1, 2);
        lrow[0] = lrow[0]*al0 + ls0;
        lrow[1] = lrow[1]*al1 + ls1;

        __syncwarp();   // P visible within the warp

        // ---- O += P @ V ----
#pragma unroll
        for (int kk = 0; kk < 64; kk += 8) {
            const float* ap = &Ps[(rb + g)*PS_ST + kk + t4];
            uint32_t a0 = __float_as_uint(ap[0]);
            uint32_t a1 = __float_as_uint(ap[8*PS_ST]);
            uint32_t a2 = __float_as_uint(ap[4]);
            uint32_t a3 = __float_as_uint(ap[8*PS_ST + 4]);
#pragma unroll
            for (int nt = 0; nt < 8; nt++) {
                const float* bp = &Vs[(kk + t4)*VS_ST + nt*8 + g];
                uint32_t b0 = __float_as_uint(bp[0]);
                uint32_t b1 = __float_as_uint(bp[4*VS_ST]);
                MMA_TF32(o[nt], a0, a1, a2, a3, b0, b1);
            }
        }
    }

    // ---- epilogue: normalize, write tf32 bits (feeds proj GEMM) ----
    const float inv0 = 1.0f / lrow[0], inv1 = 1.0f / lrow[1];
    const size_t r0 = (size_t)b*T_ + m0 + rb + g;
    const size_t r1 = r0 + 8;
#pragma unroll
    for (int nt = 0; nt < 8; nt++) {
        const int c = h*HD_ + nt*8 + 2*t4;
        *reinterpret_cast<float2*>(&att[r0*C_ + c]) =
            make_float2(__uint_as_float(f2tf32(o[nt][0] * inv0)),
                        __uint_as_float(f2tf32(o[nt][1] * inv0)));
        *reinterpret_cast<float2*>(&att[r1*C_ + c]) =
            make_float2(__uint_as_float(f2tf32(o[nt][2] * inv1)),
                        __uint_as_float(f2tf32(o[nt][3] * inv1)));
    }
}

// ---------------------------------------------------------------------------
// Launch
// ---------------------------------------------------------------------------
extern "C" void kernel_launch(void* const* d_in, const int* in_sizes, int n_in,
                              void* d_out, int out_size) {
    const float* x     = (const float*)d_in[0];
    const float* Wqkv  = (const float*)d_in[1];
    const float* bqkv  = (const float*)d_in[2];
    const float* Wproj = (const float*)d_in[3];
    const float* bproj = (const float*)d_in[4];
    float* out = (float*)d_out;

    float *qkv_p, *att_p, *xt_p, *wq_p, *wp_p;
    cudaGetSymbolAddress((void**)&qkv_p, g_qkv);
    cudaGetSymbolAddress((void**)&att_p, g_att);
    cudaGetSymbolAddress((void**)&xt_p,  g_xt);
    cudaGetSymbolAddress((void**)&wq_p,  g_wqkvt);
    cudaGetSymbolAddress((void**)&wp_p,  g_wprojt);

    cudaFuncSetAttribute(gemm_db<true>,
                         cudaFuncAttributeMaxDynamicSharedMemorySize, GEMM_SMEM);
    cudaFuncSetAttribute(gemm_db<false>,
                         cudaFuncAttributeMaxDynamicSharedMemorySize, GEMM_SMEM);
    cudaFuncSetAttribute(attn_tc,
                         cudaFuncAttributeMaxDynamicSharedMemorySize, ATTN_SMEM);

    // 0) pre-convert operands to tf32
    {
        int n4x = M_*C_/4, n4q = C_*NQKV_/4, n4p = C_*C_/4;
        cvt_kernel<<<n4x/256, 256>>>((const float4*)x,     (float4*)xt_p, n4x);
        cvt_kernel<<<n4q/256, 256>>>((const float4*)Wqkv,  (float4*)wq_p, n4q);
        cvt_kernel<<<n4p/256, 256>>>((const float4*)Wproj, (float4*)wp_p, n4p);
    }

    // 1) QKV GEMM (output kept in tf32 bits for attention)
    dim3 g1(NQKV_/128, M_/128);
    gemm_db<true><<<g1, 256, GEMM_SMEM>>>(xt_p, wq_p, bqkv, qkv_p, M_, NQKV_, C_);

    // 2) Flash attention (tensor cores, cp.async pipelined), writes tf32 bits
    dim3 g2(T_/128, B_*NH_);
    attn_tc<<<g2, 256, ATTN_SMEM>>>(qkv_p, att_p);

    // 3) Output projection (fp32 output)
    dim3 g3(C_/128, M_/128);
    gemm_db<false><<<g3, 256, GEMM_SMEM>>>(att_p, wp_p, bproj, out, M_, C_, C_);
}

// round 6
// speedup vs baseline: 3.0410x; 1.0765x over previous
#include <cuda_runtime.h>
#include <cstdint>

// Problem constants
#define B_    2
#define T_    2048
#define C_    1024
#define NH_   16
#define HD_   64
#define M_    (B_ * T_)     // 4096
#define NQKV_ (3 * C_)      // 3072

// Scratch (device globals: allocation-free)
__device__ float g_qkv[(size_t)M_ * NQKV_];      // qkv activations (tf32 bits, d-permuted)
__device__ float g_att[(size_t)M_ * C_];         // attention out  (tf32 bits, k-permuted)
__device__ float g_xt [(size_t)M_ * C_];         // x   -> tf32, k-permuted
__device__ float g_wqkvt[(size_t)C_ * NQKV_];    // Wqkv^T -> tf32 [N][K], k-permuted
__device__ float g_wprojt[(size_t)C_ * C_];      // Wproj^T -> tf32 [N][K], k-permuted

// ---------------------------------------------------------------------------
// helpers
// ---------------------------------------------------------------------------
__device__ __forceinline__ uint32_t f2tf32(float f) {
    uint32_t u;
    asm volatile("cvt.rna.tf32.f32 %0, %1;" : "=r"(u) : "f"(f));
    return u;
}
__device__ __forceinline__ float tf32f(float f) { return __uint_as_float(f2tf32(f)); }
__device__ __forceinline__ float ex2f(float x) {
    float y;
    asm volatile("ex2.approx.ftz.f32 %0, %1;" : "=f"(y) : "f"(x));
    return y;
}
__device__ __forceinline__ void cp16(uint32_t dsm, const void* src) {
    asm volatile("cp.async.ca.shared.global [%0], [%1], 16;" :: "r"(dsm), "l"(src));
}
#define CP_COMMIT() asm volatile("cp.async.commit_group;")
#define CP_WAIT1()  asm volatile("cp.async.wait_group 1;")
#define CP_WAIT0()  asm volatile("cp.async.wait_group 0;")

// within-8 k-permutation: storage position of true k.  p(k)=((k&3)<<1)|(k>>2)
// -> mma slots (t4, t4+4) sit at adjacent storage positions (2*t4, 2*t4+1).
__device__ __host__ __forceinline__ int perm8(int k) { return ((k & 3) << 1) | (k >> 2); }

#define MMA_TF32(d, a0,a1,a2,a3, b0,b1)                                   \
    asm volatile("mma.sync.aligned.m16n8k8.row.col.f32.tf32.tf32.f32 "    \
        "{%0,%1,%2,%3}, {%4,%5,%6,%7}, {%8,%9}, {%0,%1,%2,%3};"           \
        : "+f"((d)[0]), "+f"((d)[1]), "+f"((d)[2]), "+f"((d)[3])          \
        : "r"(a0), "r"(a1), "r"(a2), "r"(a3), "r"(b0), "r"(b1))

// ---------------------------------------------------------------------------
// cvt kernels: fp32 -> tf32 with within-8 k-permute; weights also transposed.
// ---------------------------------------------------------------------------
// x: row-major, permute groups of 8 along the row. One thread = one 8-group.
__global__ void cvt_x_perm(const float4* __restrict__ in,
                           float4* __restrict__ out, int n8) {
    int i = blockIdx.x * blockDim.x + threadIdx.x;
    if (i < n8) {
        float4 u = in[2*i], v = in[2*i + 1];
        float4 o0, o1;   // positions 0..3 <- k {0,4,1,5}; 4..7 <- k {2,6,3,7}
        o0.x = tf32f(u.x); o0.y = tf32f(v.x); o0.z = tf32f(u.y); o0.w = tf32f(v.y);
        o1.x = tf32f(u.z); o1.y = tf32f(v.z); o1.z = tf32f(u.w); o1.w = tf32f(v.w);
        out[2*i] = o0; out[2*i + 1] = o1;
    }
}

// W [K][N] -> W' [N][K] (k-permuted within 8-groups), tiled via smem.
__global__ void cvt_transpose_perm(const float* __restrict__ in,
                                   float* __restrict__ out, int K, int N) {
    __shared__ float t[32][33];
    const int k0 = blockIdx.y * 32, n0 = blockIdx.x * 32;
    const int tx = threadIdx.x, ty = threadIdx.y;
#pragma unroll
    for (int i = 0; i < 4; i++)
        t[ty + 8*i][tx] = in[(size_t)(k0 + ty + 8*i) * N + n0 + tx];
    __syncthreads();
    const int kp = (tx & ~7) | perm8(tx & 7);
#pragma unroll
    for (int i = 0; i < 4; i++) {
        int n = ty + 8*i;
        out[(size_t)(n0 + n) * K + k0 + kp] = tf32f(t[tx][n]);
    }
}

// ---------------------------------------------------------------------------
// TF32 GEMM + bias.  C[M,N] = A[M,K] @ B'[N,K]^T + bias.
// A, B' both k-permuted in gmem.  128x128x32 tiles, 8 warps (2x4),
// warp tile 64x32, 2-stage cp.async (R4 structure).
// Both smem tiles [row][32k] stride 40 (==8 mod 32): LDS.64 fragment loads
// conflict-free (bankpair 4g+t4 distinct per 16-lane phase).
// PERM_OUT: write columns k-permuted + tf32-rounded (feeds attention).
// ---------------------------------------------------------------------------
#define GST 40
#define STG (128 * GST)                    // floats per operand per stage
#define GEMM_SMEM (2 * 2 * STG * 4)        // 81920 B

template<bool PERM_OUT>
__global__ __launch_bounds__(256, 2)
void gemm_tc(const float* __restrict__ A, const float* __restrict__ Bm,
             const float* __restrict__ bias, float* __restrict__ Cm,
             int M, int N, int K) {
    extern __shared__ float smg[];

    const int tid  = threadIdx.x;
    const int lane = tid & 31, warp = tid >> 5;
    const int wm = warp >> 2, wn = warp & 3;
    const int g  = lane >> 2, t4 = lane & 3;
    const int row0 = blockIdx.y * 128, col0 = blockIdx.x * 128;

    const uint32_t sbase = (uint32_t)__cvta_generic_to_shared(smg);

    auto issue = [&](int kt) {
        const int buf = kt & 1;
        const uint32_t sA = sbase + (uint32_t)(buf * 2 * STG) * 4;
        const uint32_t sB = sA + (uint32_t)STG * 4;
#pragma unroll
        for (int i = 0; i < 4; i++) {
            int idx = tid + 256 * i;
            int r = idx >> 3, kc = (idx & 7) << 2;
            cp16(sA + (uint32_t)(r * GST + kc) * 4,
                 &A[(size_t)(row0 + r) * K + kt * 32 + kc]);
        }
#pragma unroll
        for (int i = 0; i < 4; i++) {
            int idx = tid + 256 * i;
            int r = idx >> 3, kc = (idx & 7) << 2;
            cp16(sB + (uint32_t)(r * GST + kc) * 4,
                 &Bm[(size_t)(col0 + r) * K + kt * 32 + kc]);
        }
    };

    float acc[4][4][4];
#pragma unroll
    for (int mt = 0; mt < 4; mt++)
#pragma unroll
        for (int nt = 0; nt < 4; nt++)
#pragma unroll
            for (int c = 0; c < 4; c++) acc[mt][nt][c] = 0.f;

    const int KT = K >> 5;
    issue(0); CP_COMMIT();

    for (int kt = 0; kt < KT; kt++) {
        if (kt + 1 < KT) issue(kt + 1);
        CP_COMMIT();
        CP_WAIT1();
        __syncthreads();

        const float* Ab = smg + (kt & 1) * 2 * STG;
        const float* Bb = Ab + STG;

#pragma unroll
        for (int kk = 0; kk < 32; kk += 8) {
            uint32_t ra[4][4], rb[4][2];
#pragma unroll
            for (int mt = 0; mt < 4; mt++) {
                const float* ap = Ab + (wm*64 + mt*16 + g) * GST + kk + 2*t4;
                float2 p0 = *reinterpret_cast<const float2*>(ap);
                float2 p1 = *reinterpret_cast<const float2*>(ap + 8*GST);
                ra[mt][0] = __float_as_uint(p0.x);   // (g,   t4)
                ra[mt][2] = __float_as_uint(p0.y);   // (g,   t4+4)
                ra[mt][1] = __float_as_uint(p1.x);   // (g+8, t4)
                ra[mt][3] = __float_as_uint(p1.y);   // (g+8, t4+4)
            }
#pragma unroll
            for (int nt = 0; nt < 4; nt++) {
                const float* bp = Bb + (wn*32 + nt*8 + g) * GST + kk + 2*t4;
                float2 pb = *reinterpret_cast<const float2*>(bp);
                rb[nt][0] = __float_as_uint(pb.x);   // (t4,   n g)
                rb[nt][1] = __float_as_uint(pb.y);   // (t4+4, n g)
            }
#pragma unroll
            for (int mt = 0; mt < 4; mt++)
#pragma unroll
                for (int nt = 0; nt < 4; nt++)
                    MMA_TF32(acc[mt][nt], ra[mt][0], ra[mt][1], ra[mt][2],
                             ra[mt][3], rb[nt][0], rb[nt][1]);
        }
        __syncthreads();
    }

    // epilogue: + bias (true columns); PERM_OUT scatters within 8-groups
    const int pos0 = perm8(2 * t4);   // position of col 2t4; col 2t4+1 at pos0+2
#pragma unroll
    for (int mt = 0; mt < 4; mt++) {
        const int rA = row0 + wm*64 + mt*16 + g;
        const int rB = rA + 8;
#pragma unroll
        for (int nt = 0; nt < 4; nt++) {
            const int cb = col0 + wn*32 + nt*8;
            const int c  = cb + 2*t4;
            const float b0 = bias[c], b1 = bias[c + 1];
            float v0 = acc[mt][nt][0] + b0, v1 = acc[mt][nt][1] + b1;
            float v2 = acc[mt][nt][2] + b0, v3 = acc[mt][nt][3] + b1;
            if (PERM_OUT) {
                Cm[(size_t)rA * N + cb + pos0]     = tf32f(v0);
                Cm[(size_t)rA * N + cb + pos0 + 2] = tf32f(v1);
                Cm[(size_t)rB * N + cb + pos0]     = tf32f(v2);
                Cm[(size_t)rB * N + cb + pos0 + 2] = tf32f(v3);
            } else {
                *reinterpret_cast<float2*>(&Cm[(size_t)rA * N + c]) = make_float2(v0, v1);
                *reinterpret_cast<float2*>(&Cm[(size_t)rB * N + c]) = make_float2(v2, v3);
            }
        }
    }
}

// ---------------------------------------------------------------------------
// Tensor-core flash attention, cp.async double-buffered K/V.
// qkv arrives d-permuted (within 8-groups) -> Q/K fragments are LDS.64.
// P staged j-permuted -> PV A-fragments LDS.64.  Output written in permuted
// position space == k-permuted att, exactly what the proj GEMM consumes.
// ---------------------------------------------------------------------------
#define QS_ST 72
#define KS_ST 72
#define VS_ST 72
#define PS_ST 72
#define KV_TILE (64 * KS_ST + 64 * VS_ST)
#define ATTN_SMEM ((128*QS_ST + 2*KV_TILE + 128*PS_ST) * 4)   // 147456 B

#define MASKVAL (-6e30f)
#define MINIT   (-1e30f)

__global__ __launch_bounds__(256, 1)
void attn_tc(const float* __restrict__ qkv, float* __restrict__ att) {
    extern __shared__ float sm[];
    float* Qs  = sm;                        // [128][QS_ST]
    float* KV0 = Qs + 128*QS_ST;            // 2 stages of K[64]+V[64]
    float* Ps  = KV0 + 2*KV_TILE;           // [128][PS_ST]

    const int tid  = threadIdx.x;
    const int lane = tid & 31, warp = tid >> 5;
    const int g = lane >> 2, t4 = lane & 3;
    const int qb = gridDim.x - 1 - blockIdx.x;   // heavy tiles first
    const int bh = blockIdx.y;
    const int b = bh >> 4, h = bh & 15;
    const int m0 = qb * 128;
    const int rb = warp * 16;
    const int pos0 = perm8(2 * t4);

    const float* qbase = qkv + ((size_t)b*T_ + m0)*NQKV_ + h*HD_;
    const float* kbase = qkv + (size_t)b*T_*NQKV_ + h*HD_ + C_;
    const float* vbase = kbase + C_;

    const uint32_t skv = (uint32_t)__cvta_generic_to_shared(KV0);

    auto issue = [&](int kvb) {
        const uint32_t sK = skv + (uint32_t)((kvb & 1) * KV_TILE) * 4;
        const uint32_t sV = sK + (uint32_t)(64 * KS_ST) * 4;
        const int jb = kvb * 64;
#pragma unroll
        for (int i = 0; i < 4; i++) {
            int idx = tid + 256 * i;
            int j = idx >> 4, d4 = (idx & 15) << 2;
            cp16(sK + (uint32_t)(j*KS_ST + d4) * 4, &kbase[(size_t)(jb+j)*NQKV_ + d4]);
        }
#pragma unroll
        for (int i = 0; i < 4; i++) {
            int idx = tid + 256 * i;
            int j = idx >> 4, d4 = (idx & 15) << 2;
            cp16(sV + (uint32_t)(j*VS_ST + d4) * 4, &vbase[(size_t)(jb+j)*NQKV_ + d4]);
        }
    };

    issue(0); CP_COMMIT();

    // Q tile: scale by (1/8)*log2(e), re-round, copy-through (already permuted)
    const float qscale = 0.125f * 1.44269504088896340736f;
    for (int idx = tid; idx < 128*16; idx += 256) {
        int r = idx >> 4, d4 = (idx & 15) << 2;
        float4 v = *reinterpret_cast<const float4*>(&qbase[(size_t)r*NQKV_ + d4]);
        float* q = &Qs[r*QS_ST + d4];
        q[0] = tf32f(v.x * qscale);
        q[1] = tf32f(v.y * qscale);
        q[2] = tf32f(v.z * qscale);
        q[3] = tf32f(v.w * qscale);
    }

    float o[8][4];
    float mrow[2] = {MINIT, MINIT}, lrow[2] = {0.f, 0.f};
#pragma unroll
    for (int nt = 0; nt < 8; nt++)
#pragma unroll
        for (int c = 0; c < 4; c++) o[nt][c] = 0.f;

    const int nkv = 2*qb + 2;
    for (int kvb = 0; kvb < nkv; kvb++) {
        const int jb = kvb * 64;
        CP_WAIT0();
        __syncthreads();
        if (kvb + 1 < nkv) { issue(kvb + 1); CP_COMMIT(); }

        const float* Ks = KV0 + (kvb & 1) * KV_TILE;
        const float* Vs = Ks + 64 * KS_ST;

        if (jb > m0 + rb + 15) continue;

        // ---- S = Q' @ K^T (both d-permuted: dot product invariant) ----
        float s[8][4];
#pragma unroll
        for (int nt = 0; nt < 8; nt++)
#pragma unroll
            for (int c = 0; c < 4; c++) s[nt][c] = 0.f;

#pragma unroll
        for (int kk = 0; kk < 64; kk += 8) {
            const float* ap = &Qs[(rb + g)*QS_ST + kk + 2*t4];
            float2 qa0 = *reinterpret_cast<const float2*>(ap);
            float2 qa1 = *reinterpret_cast<const float2*>(ap + 8*QS_ST);
            uint32_t a0 = __float_as_uint(qa0.x), a2 = __float_as_uint(qa0.y);
            uint32_t a1 = __float_as_uint(qa1.x), a3 = __float_as_uint(qa1.y);
#pragma unroll
            for (int nt = 0; nt < 8; nt++) {
                float2 kf = *reinterpret_cast<const float2*>(
                    &Ks[(nt*8 + g)*KS_ST + kk + 2*t4]);
                MMA_TF32(s[nt], a0, a1, a2, a3,
                         __float_as_uint(kf.x), __float_as_uint(kf.y));
            }
        }

        // ---- causal mask (true j coordinates; K rows are natural) ----
        if (jb + 63 > m0 + rb) {
            const int r0 = m0 + rb + g, r1 = r0 + 8;
#pragma unroll
            for (int nt = 0; nt < 8; nt++) {
                int cb = jb + nt*8 + 2*t4;
                if (cb     > r0) s[nt][0] = MASKVAL;
                if (cb + 1 > r0) s[nt][1] = MASKVAL;
                if (cb     > r1) s[nt][2] = MASKVAL;
                if (cb + 1 > r1) s[nt][3] = MASKVAL;
            }
        }

        // ---- online softmax (exp2 domain) ----
        float mx0 = MINIT, mx1 = MINIT;
#pragma unroll
        for (int nt = 0; nt < 8; nt++) {
            mx0 = fmaxf(mx0, fmaxf(s[nt][0], s[nt][1]));
            mx1 = fmaxf(mx1, fmaxf(s[nt][2], s[nt][3]));
        }
        mx0 = fmaxf(mx0, __shfl_xor_sync(0xffffffffu, mx0, 1));
        mx0 = fmaxf(mx0, __shfl_xor_sync(0xffffffffu, mx0, 2));
        mx1 = fmaxf(mx1, __shfl_xor_sync(0xffffffffu, mx1, 1));
        mx1 = fmaxf(mx1, __shfl_xor_sync(0xffffffffu, mx1, 2));
        const float mn0 = fmaxf(mrow[0], mx0), mn1 = fmaxf(mrow[1], mx1);
        const float al0 = ex2f(mrow[0] - mn0), al1 = ex2f(mrow[1] - mn1);
        mrow[0] = mn0; mrow[1] = mn1;

        float ls0 = 0.f, ls1 = 0.f;
#pragma unroll
        for (int nt = 0; nt < 8; nt++) {
            s[nt][0] = ex2f(s[nt][0] - mn0);
            s[nt][1] = ex2f(s[nt][1] - mn0);
            s[nt][2] = ex2f(s[nt][2] - mn1);
            s[nt][3] = ex2f(s[nt][3] - mn1);
            ls0 += s[nt][0] + s[nt][1];
            ls1 += s[nt][2] + s[nt][3];
            o[nt][0] *= al0; o[nt][1] *= al0;
            o[nt][2] *= al1; o[nt][3] *= al1;
            // stage P j-permuted (tf32) for LDS.64 PV fragments
            float* p0 = &Ps[(rb + g)*PS_ST + nt*8];
            float* p1 = &Ps[(rb + g + 8)*PS_ST + nt*8];
            p0[pos0]     = tf32f(s[nt][0]);
            p0[pos0 + 2] = tf32f(s[nt][1]);
            p1[pos0]     = tf32f(s[nt][2]);
            p1[pos0 + 2] = tf32f(s[nt][3]);
        }
        ls0 += __shfl_xor_sync(0xffffffffu, ls0, 1);
        ls0 += __shfl_xor_sync(0xffffffffu, ls0, 2);
        ls1 += __shfl_xor_sync(0xffffffffu, ls1, 1);
        ls1 += __shfl_xor_sync(0xffffffffu, ls1, 2);
        lrow[0] = lrow[0]*al0 + ls0;
        lrow[1] = lrow[1]*al1 + ls1;

        __syncwarp();

        // ---- O += P @ V  (A j-permuted storage <-> V natural rows) ----
#pragma unroll
        for (int kk = 0; kk < 64; kk += 8) {
            const float* ap = &Ps[(rb + g)*PS_ST + kk + 2*t4];
            float2 pa0 = *reinterpret_cast<const float2*>(ap);
            float2 pa1 = *reinterpret_cast<const float2*>(ap + 8*PS_ST);
            uint32_t a0 = __float_as_uint(pa0.x), a2 = __float_as_uint(pa0.y);
            uint32_t a1 = __float_as_uint(pa1.x), a3 = __float_as_uint(pa1.y);
#pragma unroll
            for (int nt = 0; nt < 8; nt++) {
                const float* bp = &Vs[(kk + t4)*VS_ST + nt*8 + g];
                MMA_TF32(o[nt], a0, a1, a2, a3,
                         __float_as_uint(bp[0]), __float_as_uint(bp[4*VS_ST]));
            }
        }
    }

    // ---- epilogue: normalize; position-space write == permuted att ----
    const float inv0 = 1.0f / lrow[0], inv1 = 1.0f / lrow[1];
    const size_t r0 = (size_t)b*T_ + m0 + rb + g;
    const size_t r1 = r0 + 8;
#pragma unroll
    for (int nt = 0; nt < 8; nt++) {
        const int c = h*HD_ + nt*8 + 2*t4;
        *reinterpret_cast<float2*>(&att[r0*C_ + c]) =
            make_float2(tf32f(o[nt][0] * inv0), tf32f(o[nt][1] * inv0));
        *reinterpret_cast<float2*>(&att[r1*C_ + c]) =
            make_float2(tf32f(o[nt][2] * inv1), tf32f(o[nt][3] * inv1));
    }
}

// ---------------------------------------------------------------------------
// Launch
// ---------------------------------------------------------------------------
extern "C" void kernel_launch(void* const* d_in, const int* in_sizes, int n_in,
                              void* d_out, int out_size) {
    const float* x     = (const float*)d_in[0];
    const float* Wqkv  = (const float*)d_in[1];
    const float* bqkv  = (const float*)d_in[2];
    const float* Wproj = (const float*)d_in[3];
    const float* bproj = (const float*)d_in[4];
    float* out = (float*)d_out;

    float *qkv_p, *att_p, *xt_p, *wq_p, *wp_p;
    cudaGetSymbolAddress((void**)&qkv_p, g_qkv);
    cudaGetSymbolAddress((void**)&att_p, g_att);
    cudaGetSymbolAddress((void**)&xt_p,  g_xt);
    cudaGetSymbolAddress((void**)&wq_p,  g_wqkvt);
    cudaGetSymbolAddress((void**)&wp_p,  g_wprojt);

    cudaFuncSetAttribute(gemm_tc<true>,
                         cudaFuncAttributeMaxDynamicSharedMemorySize, GEMM_SMEM);
    cudaFuncSetAttribute(gemm_tc<false>,
                         cudaFuncAttributeMaxDynamicSharedMemorySize, GEMM_SMEM);
    cudaFuncSetAttribute(attn_tc,
                         cudaFuncAttributeMaxDynamicSharedMemorySize, ATTN_SMEM);

    // 0) operand prep: x k-permuted; weights transposed [N][K] + k-permuted
    cvt_x_perm<<<(M_*C_/8)/256, 256>>>((const float4*)x, (float4*)xt_p, M_*C_/8);
    {
        dim3 blk(32, 8);
        dim3 gq(NQKV_/32, C_/32);
        cvt_transpose_perm<<<gq, blk>>>(Wqkv, wq_p, C_, NQKV_);
        dim3 gp(C_/32, C_/32);
        cvt_transpose_perm<<<gp, blk>>>(Wproj, wp_p, C_, C_);
    }

    // 1) QKV GEMM -> d-permuted tf32 qkv
    dim3 g1(NQKV_/128, M_/128);
    gemm_tc<true><<<g1, 256, GEMM_SMEM>>>(xt_p, wq_p, bqkv, qkv_p, M_, NQKV_, C_);

    // 2) Flash attention -> k-permuted tf32 att
    dim3 g2(T_/128, B_*NH_);
    attn_tc<<<g2, 256, ATTN_SMEM>>>(qkv_p, att_p);

    // 3) Output projection -> natural fp32 out
    dim3 g3(C_/128, M_/128);
    gemm_tc<false><<<g3, 256, GEMM_SMEM>>>(att_p, wp_p, bproj, out, M_, C_, C_);
}

// round 7
// speedup vs baseline: 3.1622x; 1.0399x over previous
#include <cuda_runtime.h>
#include <cstdint>

// Problem constants
#define B_    2
#define T_    2048
#define C_    1024
#define NH_   16
#define HD_   64
#define M_    (B_ * T_)     // 4096
#define NQKV_ (3 * C_)      // 3072

// Scratch (device globals: allocation-free)
__device__ float g_qkv[(size_t)M_ * NQKV_];      // qkv activations (tf32 bits, d-permuted)
__device__ float g_att[(size_t)M_ * C_];         // attention out  (tf32 bits, k-permuted)
__device__ float g_xt [(size_t)M_ * C_];         // x   -> tf32, k-permuted
__device__ float g_wqkvt[(size_t)C_ * NQKV_];    // Wqkv^T -> tf32 [N][K], k-permuted
__device__ float g_wprojt[(size_t)C_ * C_];      // Wproj^T -> tf32 [N][K], k-permuted

// ---------------------------------------------------------------------------
// helpers
// ---------------------------------------------------------------------------
__device__ __forceinline__ uint32_t f2tf32(float f) {
    uint32_t u;
    asm volatile("cvt.rna.tf32.f32 %0, %1;" : "=r"(u) : "f"(f));
    return u;
}
__device__ __forceinline__ float tf32f(float f) { return __uint_as_float(f2tf32(f)); }
__device__ __forceinline__ float ex2f(float x) {
    float y;
    asm volatile("ex2.approx.ftz.f32 %0, %1;" : "=f"(y) : "f"(x));
    return y;
}
__device__ __forceinline__ void cp16(uint32_t dsm, const void* src) {
    asm volatile("cp.async.ca.shared.global [%0], [%1], 16;" :: "r"(dsm), "l"(src));
}
#define CP_COMMIT() asm volatile("cp.async.commit_group;")
#define CP_WAIT1()  asm volatile("cp.async.wait_group 1;")
#define CP_WAIT0()  asm volatile("cp.async.wait_group 0;")

// within-8 k-permutation: storage position of true k.  p(k)=((k&3)<<1)|(k>>2)
// -> mma slots (t4, t4+4) sit at adjacent storage positions (2*t4, 2*t4+1).
__device__ __host__ __forceinline__ int perm8(int k) { return ((k & 3) << 1) | (k >> 2); }

#define MMA_TF32(d, a0,a1,a2,a3, b0,b1)                                   \
    asm volatile("mma.sync.aligned.m16n8k8.row.col.f32.tf32.tf32.f32 "    \
        "{%0,%1,%2,%3}, {%4,%5,%6,%7}, {%8,%9}, {%0,%1,%2,%3};"           \
        : "+f"((d)[0]), "+f"((d)[1]), "+f"((d)[2]), "+f"((d)[3])          \
        : "r"(a0), "r"(a1), "r"(a2), "r"(a3), "r"(b0), "r"(b1))

// ---------------------------------------------------------------------------
// cvt kernels: fp32 -> tf32 with within-8 k-permute; weights also transposed.
// ---------------------------------------------------------------------------
__global__ void cvt_x_perm(const float4* __restrict__ in,
                           float4* __restrict__ out, int n8) {
    int i = blockIdx.x * blockDim.x + threadIdx.x;
    if (i < n8) {
        float4 u = in[2*i], v = in[2*i + 1];
        float4 o0, o1;   // positions 0..3 <- k {0,4,1,5}; 4..7 <- k {2,6,3,7}
        o0.x = tf32f(u.x); o0.y = tf32f(v.x); o0.z = tf32f(u.y); o0.w = tf32f(v.y);
        o1.x = tf32f(u.z); o1.y = tf32f(v.z); o1.z = tf32f(u.w); o1.w = tf32f(v.w);
        out[2*i] = o0; out[2*i + 1] = o1;
    }
}

// W [K][N] -> W' [N][K] (k-permuted within 8-groups), tiled via smem.
__global__ void cvt_transpose_perm(const float* __restrict__ in,
                                   float* __restrict__ out, int K, int N) {
    __shared__ float t[32][33];
    const int k0 = blockIdx.y * 32, n0 = blockIdx.x * 32;
    const int tx = threadIdx.x, ty = threadIdx.y;
#pragma unroll
    for (int i = 0; i < 4; i++)
        t[ty + 8*i][tx] = in[(size_t)(k0 + ty + 8*i) * N + n0 + tx];
    __syncthreads();
    const int kp = (tx & ~7) | perm8(tx & 7);
#pragma unroll
    for (int i = 0; i < 4; i++) {
        int n = ty + 8*i;
        out[(size_t)(n0 + n) * K + k0 + kp] = tf32f(t[tx][n]);
    }
}

// ---------------------------------------------------------------------------
// TF32 GEMM + bias.  C[M,N] = A[M,K] @ B'[N,K]^T + bias.
// 128 threads / 4 warps, warp tile 64x64 (2x2 warp grid), 128x128x32 block
// tile, 2-stage cp.async.  Per kk-step: 32 MMAs vs 16 LDS.64 per warp.
// __launch_bounds__(128,2): 256-reg budget (acc=128 + frags ~32), 2 CTA/SM.
// Smem [row][32k] stride 40 (==8 mod 32): LDS.64 fragment loads conflict-free.
// PERM_OUT: write columns k-permuted + tf32-rounded (feeds attention).
// ---------------------------------------------------------------------------
#define GST 40
#define STG (128 * GST)                    // floats per operand per stage
#define GEMM_SMEM (2 * 2 * STG * 4)        // 81920 B

template<bool PERM_OUT>
__global__ __launch_bounds__(128, 2)
void gemm_tc(const float* __restrict__ A, const float* __restrict__ Bm,
             const float* __restrict__ bias, float* __restrict__ Cm,
             int M, int N, int K) {
    extern __shared__ float smg[];

    const int tid  = threadIdx.x;
    const int lane = tid & 31, warp = tid >> 5;
    const int wm = warp >> 1, wn = warp & 1;     // 2x2 warp grid, 64x64 tiles
    const int g  = lane >> 2, t4 = lane & 3;
    const int row0 = blockIdx.y * 128, col0 = blockIdx.x * 128;

    const uint32_t sbase = (uint32_t)__cvta_generic_to_shared(smg);

    auto issue = [&](int kt) {
        const int buf = kt & 1;
        const uint32_t sA = sbase + (uint32_t)(buf * 2 * STG) * 4;
        const uint32_t sB = sA + (uint32_t)STG * 4;
#pragma unroll
        for (int i = 0; i < 8; i++) {
            int idx = tid + 128 * i;
            int r = idx >> 3, kc = (idx & 7) << 2;
            cp16(sA + (uint32_t)(r * GST + kc) * 4,
                 &A[(size_t)(row0 + r) * K + kt * 32 + kc]);
        }
#pragma unroll
        for (int i = 0; i < 8; i++) {
            int idx = tid + 128 * i;
            int r = idx >> 3, kc = (idx & 7) << 2;
            cp16(sB + (uint32_t)(r * GST + kc) * 4,
                 &Bm[(size_t)(col0 + r) * K + kt * 32 + kc]);
        }
    };

    float acc[4][8][4];
#pragma unroll
    for (int mt = 0; mt < 4; mt++)
#pragma unroll
        for (int nt = 0; nt < 8; nt++)
#pragma unroll
            for (int c = 0; c < 4; c++) acc[mt][nt][c] = 0.f;

    const int KT = K >> 5;
    issue(0); CP_COMMIT();

    for (int kt = 0; kt < KT; kt++) {
        if (kt + 1 < KT) issue(kt + 1);
        CP_COMMIT();
        CP_WAIT1();
        __syncthreads();

        const float* Ab = smg + (kt & 1) * 2 * STG;
        const float* Bb = Ab + STG;

#pragma unroll
        for (int kk = 0; kk < 32; kk += 8) {
            uint32_t ra[4][4], rb[8][2];
#pragma unroll
            for (int mt = 0; mt < 4; mt++) {
                const float* ap = Ab + (wm*64 + mt*16 + g) * GST + kk + 2*t4;
                float2 p0 = *reinterpret_cast<const float2*>(ap);
                float2 p1 = *reinterpret_cast<const float2*>(ap + 8*GST);
                ra[mt][0] = __float_as_uint(p0.x);   // (g,   t4)
                ra[mt][2] = __float_as_uint(p0.y);   // (g,   t4+4)
                ra[mt][1] = __float_as_uint(p1.x);   // (g+8, t4)
                ra[mt][3] = __float_as_uint(p1.y);   // (g+8, t4+4)
            }
#pragma unroll
            for (int nt = 0; nt < 8; nt++) {
                const float* bp = Bb + (wn*64 + nt*8 + g) * GST + kk + 2*t4;
                float2 pb = *reinterpret_cast<const float2*>(bp);
                rb[nt][0] = __float_as_uint(pb.x);   // (t4,   n g)
                rb[nt][1] = __float_as_uint(pb.y);   // (t4+4, n g)
            }
#pragma unroll
            for (int mt = 0; mt < 4; mt++)
#pragma unroll
                for (int nt = 0; nt < 8; nt++)
                    MMA_TF32(acc[mt][nt], ra[mt][0], ra[mt][1], ra[mt][2],
                             ra[mt][3], rb[nt][0], rb[nt][1]);
        }
        __syncthreads();
    }

    // epilogue: + bias (true columns); PERM_OUT scatters within 8-groups
    const int pos0 = perm8(2 * t4);   // position of col 2t4; col 2t4+1 at pos0+2
#pragma unroll
    for (int mt = 0; mt < 4; mt++) {
        const int rA = row0 + wm*64 + mt*16 + g;
        const int rB = rA + 8;
#pragma unroll
        for (int nt = 0; nt < 8; nt++) {
            const int cb = col0 + wn*64 + nt*8;
            const int c  = cb + 2*t4;
            const float b0 = bias[c], b1 = bias[c + 1];
            float v0 = acc[mt][nt][0] + b0, v1 = acc[mt][nt][1] + b1;
            float v2 = acc[mt][nt][2] + b0, v3 = acc[mt][nt][3] + b1;
            if (PERM_OUT) {
                Cm[(size_t)rA * N + cb + pos0]     = tf32f(v0);
                Cm[(size_t)rA * N + cb + pos0 + 2] = tf32f(v1);
                Cm[(size_t)rB * N + cb + pos0]     = tf32f(v2);
                Cm[(size_t)rB * N + cb + pos0 + 2] = tf32f(v3);
            } else {
                *reinterpret_cast<float2*>(&Cm[(size_t)rA * N + c]) = make_float2(v0, v1);
                *reinterpret_cast<float2*>(&Cm[(size_t)rB * N + c]) = make_float2(v2, v3);
            }
        }
    }
}

// ---------------------------------------------------------------------------
// Tensor-core flash attention, cp.async double-buffered K/V.
// qkv arrives d-permuted (within 8-groups) -> Q/K fragments are LDS.64.
// P staged j-permuted -> PV A-fragments LDS.64.  Output written in permuted
// position space == k-permuted att, exactly what the proj GEMM consumes.
// ---------------------------------------------------------------------------
#define QS_ST 72
#define KS_ST 72
#define VS_ST 72
#define PS_ST 72
#define KV_TILE (64 * KS_ST + 64 * VS_ST)
#define ATTN_SMEM ((128*QS_ST + 2*KV_TILE + 128*PS_ST) * 4)   // 147456 B

#define MASKVAL (-6e30f)
#define MINIT   (-1e30f)

__global__ __launch_bounds__(256, 1)
void attn_tc(const float* __restrict__ qkv, float* __restrict__ att) {
    extern __shared__ float sm[];
    float* Qs  = sm;                        // [128][QS_ST]
    float* KV0 = Qs + 128*QS_ST;            // 2 stages of K[64]+V[64]
    float* Ps  = KV0 + 2*KV_TILE;           // [128][PS_ST]

    const int tid  = threadIdx.x;
    const int lane = tid & 31, warp = tid >> 5;
    const int g = lane >> 2, t4 = lane & 3;
    const int qb = gridDim.x - 1 - blockIdx.x;   // heavy tiles first
    const int bh = blockIdx.y;
    const int b = bh >> 4, h = bh & 15;
    const int m0 = qb * 128;
    const int rb = warp * 16;
    const int pos0 = perm8(2 * t4);

    const float* qbase = qkv + ((size_t)b*T_ + m0)*NQKV_ + h*HD_;
    const float* kbase = qkv + (size_t)b*T_*NQKV_ + h*HD_ + C_;
    const float* vbase = kbase + C_;

    const uint32_t skv = (uint32_t)__cvta_generic_to_shared(KV0);

    auto issue = [&](int kvb) {
        const uint32_t sK = skv + (uint32_t)((kvb & 1) * KV_TILE) * 4;
        const uint32_t sV = sK + (uint32_t)(64 * KS_ST) * 4;
        const int jb = kvb * 64;
#pragma unroll
        for (int i = 0; i < 4; i++) {
            int idx = tid + 256 * i;
            int j = idx >> 4, d4 = (idx & 15) << 2;
            cp16(sK + (uint32_t)(j*KS_ST + d4) * 4, &kbase[(size_t)(jb+j)*NQKV_ + d4]);
        }
#pragma unroll
        for (int i = 0; i < 4; i++) {
            int idx = tid + 256 * i;
            int j = idx >> 4, d4 = (idx & 15) << 2;
            cp16(sV + (uint32_t)(j*VS_ST + d4) * 4, &vbase[(size_t)(jb+j)*NQKV_ + d4]);
        }
    };

    issue(0); CP_COMMIT();

    // Q tile: scale by (1/8)*log2(e), re-round, copy-through (already permuted)
    const float qscale = 0.125f * 1.44269504088896340736f;
    for (int idx = tid; idx < 128*16; idx += 256) {
        int r = idx >> 4, d4 = (idx & 15) << 2;
        float4 v = *reinterpret_cast<const float4*>(&qbase[(size_t)r*NQKV_ + d4]);
        float* q = &Qs[r*QS_ST + d4];
        q[0] = tf32f(v.x * qscale);
        q[1] = tf32f(v.y * qscale);
        q[2] = tf32f(v.z * qscale);
        q[3] = tf32f(v.w * qscale);
    }

    float o[8][4];
    float mrow[2] = {MINIT, MINIT}, lrow[2] = {0.f, 0.f};
#pragma unroll
    for (int nt = 0; nt < 8; nt++)
#pragma unroll
        for (int c = 0; c < 4; c++) o[nt][c] = 0.f;

    const int nkv = 2*qb + 2;
    for (int kvb = 0; kvb < nkv; kvb++) {
        const int jb = kvb * 64;
        CP_WAIT0();
        __syncthreads();
        if (kvb + 1 < nkv) { issue(kvb + 1); CP_COMMIT(); }

        const float* Ks = KV0 + (kvb & 1) * KV_TILE;
        const float* Vs = Ks + 64 * KS_ST;

        if (jb > m0 + rb + 15) continue;

        // ---- S = Q' @ K^T (both d-permuted: dot product invariant) ----
        float s[8][4];
#pragma unroll
        for (int nt = 0; nt < 8; nt++)
#pragma unroll
            for (int c = 0; c < 4; c++) s[nt][c] = 0.f;

#pragma unroll
        for (int kk = 0; kk < 64; kk += 8) {
            const float* ap = &Qs[(rb + g)*QS_ST + kk + 2*t4];
            float2 qa0 = *reinterpret_cast<const float2*>(ap);
            float2 qa1 = *reinterpret_cast<const float2*>(ap + 8*QS_ST);
            uint32_t a0 = __float_as_uint(qa0.x), a2 = __float_as_uint(qa0.y);
            uint32_t a1 = __float_as_uint(qa1.x), a3 = __float_as_uint(qa1.y);
#pragma unroll
            for (int nt = 0; nt < 8; nt++) {
                float2 kf = *reinterpret_cast<const float2*>(
                    &Ks[(nt*8 + g)*KS_ST + kk + 2*t4]);
                MMA_TF32(s[nt], a0, a1, a2, a3,
                         __float_as_uint(kf.x), __float_as_uint(kf.y));
            }
        }

        // ---- causal mask (true j coordinates; K rows are natural) ----
        if (jb + 63 > m0 + rb) {
            const int r0 = m0 + rb + g, r1 = r0 + 8;
#pragma unroll
            for (int nt = 0; nt < 8; nt++) {
                int cb = jb + nt*8 + 2*t4;
                if (cb     > r0) s[nt][0] = MASKVAL;
                if (cb + 1 > r0) s[nt][1] = MASKVAL;
                if (cb     > r1) s[nt][2] = MASKVAL;
                if (cb + 1 > r1) s[nt][3] = MASKVAL;
            }
        }

        // ---- online softmax (exp2 domain) ----
        float mx0 = MINIT, mx1 = MINIT;
#pragma unroll
        for (int nt = 0; nt < 8; nt++) {
            mx0 = fmaxf(mx0, fmaxf(s[nt][0], s[nt][1]));
            mx1 = fmaxf(mx1, fmaxf(s[nt][2], s[nt][3]));
        }
        mx0 = fmaxf(mx0, __shfl_xor_sync(0xffffffffu, mx0, 1));
        mx0 = fmaxf(mx0, __shfl_xor_sync(0xffffffffu, mx0, 2));
        mx1 = fmaxf(mx1, __shfl_xor_sync(0xffffffffu, mx1, 1));
        mx1 = fmaxf(mx1, __shfl_xor_sync(0xffffffffu, mx1, 2));
        const float mn0 = fmaxf(mrow[0], mx0), mn1 = fmaxf(mrow[1], mx1);
        const float al0 = ex2f(mrow[0] - mn0), al1 = ex2f(mrow[1] - mn1);
        mrow[0] = mn0; mrow[1] = mn1;

        float ls0 = 0.f, ls1 = 0.f;
#pragma unroll
        for (int nt = 0; nt < 8; nt++) {
            s[nt][0] = ex2f(s[nt][0] - mn0);
            s[nt][1] = ex2f(s[nt][1] - mn0);
            s[nt][2] = ex2f(s[nt][2] - mn1);
            s[nt][3] = ex2f(s[nt][3] - mn1);
            ls0 += s[nt][0] + s[nt][1];
            ls1 += s[nt][2] + s[nt][3];
            o[nt][0] *= al0; o[nt][1] *= al0;
            o[nt][2] *= al1; o[nt][3] *= al1;
            // stage P j-permuted (tf32) for LDS.64 PV fragments
            float* p0 = &Ps[(rb + g)*PS_ST + nt*8];
            float* p1 = &Ps[(rb + g + 8)*PS_ST + nt*8];
            p0[pos0]     = tf32f(s[nt][0]);
            p0[pos0 + 2] = tf32f(s[nt][1]);
            p1[pos0]     = tf32f(s[nt][2]);
            p1[pos0 + 2] = tf32f(s[nt][3]);
        }
        ls0 += __shfl_xor_sync(0xffffffffu, ls0, 1);
        ls0 += __shfl_xor_sync(0xffffffffu, ls0, 2);
        ls1 += __shfl_xor_sync(0xffffffffu, ls1, 1);
        ls1 += __shfl_xor_sync(0xffffffffu, ls1, 2);
        lrow[0] = lrow[0]*al0 + ls0;
        lrow[1] = lrow[1]*al1 + ls1;

        __syncwarp();

        // ---- O += P @ V  (A j-permuted storage <-> V natural rows) ----
#pragma unroll
        for (int kk = 0; kk < 64; kk += 8) {
            const float* ap = &Ps[(rb + g)*PS_ST + kk + 2*t4];
            float2 pa0 = *reinterpret_cast<const float2*>(ap);
            float2 pa1 = *reinterpret_cast<const float2*>(ap + 8*PS_ST);
            uint32_t a0 = __float_as_uint(pa0.x), a2 = __float_as_uint(pa0.y);
            uint32_t a1 = __float_as_uint(pa1.x), a3 = __float_as_uint(pa1.y);
#pragma unroll
            for (int nt = 0; nt < 8; nt++) {
                const float* bp = &Vs[(kk + t4)*VS_ST + nt*8 + g];
                MMA_TF32(o[nt], a0, a1, a2, a3,
                         __float_as_uint(bp[0]), __float_as_uint(bp[4*VS_ST]));
            }
        }
    }

    // ---- epilogue: normalize; position-space write == permuted att ----
    const float inv0 = 1.0f / lrow[0], inv1 = 1.0f / lrow[1];
    const size_t r0 = (size_t)b*T_ + m0 + rb + g;
    const size_t r1 = r0 + 8;
#pragma unroll
    for (int nt = 0; nt < 8; nt++) {
        const int c = h*HD_ + nt*8 + 2*t4;
        *reinterpret_cast<float2*>(&att[r0*C_ + c]) =
            make_float2(tf32f(o[nt][0] * inv0), tf32f(o[nt][1] * inv0));
        *reinterpret_cast<float2*>(&att[r1*C_ + c]) =
            make_float2(tf32f(o[nt][2] * inv1), tf32f(o[nt][3] * inv1));
    }
}

// ---------------------------------------------------------------------------
// Launch
// ---------------------------------------------------------------------------
extern "C" void kernel_launch(void* const* d_in, const int* in_sizes, int n_in,
                              void* d_out, int out_size) {
    const float* x     = (const float*)d_in[0];
    const float* Wqkv  = (const float*)d_in[1];
    const float* bqkv  = (const float*)d_in[2];
    const float* Wproj = (const float*)d_in[3];
    const float* bproj = (const float*)d_in[4];
    float* out = (float*)d_out;

    float *qkv_p, *att_p, *xt_p, *wq_p, *wp_p;
    cudaGetSymbolAddress((void**)&qkv_p, g_qkv);
    cudaGetSymbolAddress((void**)&att_p, g_att);
    cudaGetSymbolAddress((void**)&xt_p,  g_xt);
    cudaGetSymbolAddress((void**)&wq_p,  g_wqkvt);
    cudaGetSymbolAddress((void**)&wp_p,  g_wprojt);

    cudaFuncSetAttribute(gemm_tc<true>,
                         cudaFuncAttributeMaxDynamicSharedMemorySize, GEMM_SMEM);
    cudaFuncSetAttribute(gemm_tc<false>,
                         cudaFuncAttributeMaxDynamicSharedMemorySize, GEMM_SMEM);
    cudaFuncSetAttribute(attn_tc,
                         cudaFuncAttributeMaxDynamicSharedMemorySize, ATTN_SMEM);

    // 0) operand prep: x k-permuted; weights transposed [N][K] + k-permuted
    cvt_x_perm<<<(M_*C_/8)/256, 256>>>((const float4*)x, (float4*)xt_p, M_*C_/8);
    {
        dim3 blk(32, 8);
        dim3 gq(NQKV_/32, C_/32);
        cvt_transpose_perm<<<gq, blk>>>(Wqkv, wq_p, C_, NQKV_);
        dim3 gp(C_/32, C_/32);
        cvt_transpose_perm<<<gp, blk>>>(Wproj, wp_p, C_, C_);
    }

    // 1) QKV GEMM -> d-permuted tf32 qkv
    dim3 g1(NQKV_/128, M_/128);
    gemm_tc<true><<<g1, 128, GEMM_SMEM>>>(xt_p, wq_p, bqkv, qkv_p, M_, NQKV_, C_);

    // 2) Flash attention -> k-permuted tf32 att
    dim3 g2(T_/128, B_*NH_);
    attn_tc<<<g2, 256, ATTN_SMEM>>>(qkv_p, att_p);

    // 3) Output projection -> natural fp32 out
    dim3 g3(C_/128, M_/128);
    gemm_tc<false><<<g3, 128, GEMM_SMEM>>>(att_p, wp_p, bproj, out, M_, C_, C_);
}